// round 10
// baseline (speedup 1.0000x reference)
#include <cuda_runtime.h>
#include <cuda_fp16.h>
#include <math.h>

// ---------------- problem constants ----------------
constexpr int kT   = 1024;
constexpr int kD   = 1024;
constexpr int kH   = 16;
constexpr int kDH  = 64;
constexpr int kE   = 8;
constexpr int kDFF = 4096;
constexpr int kSlots = 3072;   // 2048 assignments + per-expert pad to 128

// ---------------- device scratch ----------------
__device__ float g_x[kT * kD];
__device__ float g_q[kH * kT * kDH];
__device__ float g_kT[kH * kDH * kT];   // K transposed: [h][dh][t]
__device__ float g_v[kH * kT * kDH];
__device__ float g_attn[kT * kD];
__device__ float g_emb2[kT * kD];
__device__ float g_y[kT * kD];
__device__ float g_h[kSlots * kDFF];
__device__ float g_yo[kSlots * kD];
__device__ int   g_ids[kT * 2];
__device__ float g_gates[kT * 2];
__device__ int   g_counts[kE];
__device__ int   g_poff[kE + 1];
__device__ int   g_cursor[kE];
__device__ int   g_slot_token[kSlots];
__device__ int   g_slotpos[kT * 2];
__device__ float g_impsum[kE];

// ---------------- mma helpers ----------------
__device__ __forceinline__ unsigned f2tf32(float x) {
    unsigned y; asm("cvt.rna.tf32.f32 %0, %1;" : "=r"(y) : "f"(x)); return y;
}
__device__ __forceinline__ void mma_tf32(float c[4], const unsigned a[4], const unsigned b[2]) {
    asm volatile("mma.sync.aligned.m16n8k8.row.col.f32.tf32.tf32.f32 "
        "{%0,%1,%2,%3}, {%4,%5,%6,%7}, {%8,%9}, {%0,%1,%2,%3};\n"
        : "+f"(c[0]), "+f"(c[1]), "+f"(c[2]), "+f"(c[3])
        : "r"(a[0]), "r"(a[1]), "r"(a[2]), "r"(a[3]), "r"(b[0]), "r"(b[1]));
}
__device__ __forceinline__ void mma_f16(float c[4], const unsigned a[4], const unsigned b[2]) {
    asm volatile("mma.sync.aligned.m16n8k16.row.col.f32.f16.f16.f32 "
        "{%0,%1,%2,%3}, {%4,%5,%6,%7}, {%8,%9}, {%0,%1,%2,%3};\n"
        : "+f"(c[0]), "+f"(c[1]), "+f"(c[2]), "+f"(c[3])
        : "r"(a[0]), "r"(a[1]), "r"(a[2]), "r"(a[3]), "r"(b[0]), "r"(b[1]));
}
__device__ __forceinline__ unsigned pk2(float a, float b) {
    __half2 h = __floats2half2_rn(a, b);
    return *(unsigned*)&h;
}

// fp16 GEMM tile config: block 128 threads (4 warps), block tile M=128 N=128,
// warp tile 64x64 (wm = w&1, wn = w>>1), K-panel 32 (= 2 k16 MMAs).
// A smem: [m][kpair] stride 20; B smem: [kpair][n] stride 136 (both conflict-free).
constexpr int ASTR = 20;
constexpr int BSTR = 136;

#define GEMM16_SMEM \
    __shared__ __align__(16) unsigned As[128 * ASTR]; \
    __shared__ __align__(16) unsigned Bs[16 * BSTR];

// compute one 32-deep panel: 2 k16 steps; warp tile 64x64 (4 mt x 8 nt)
#define GEMM16_COMPUTE \
    _Pragma("unroll") \
    for (int p0 = 0; p0 < 16; p0 += 8) { \
        unsigned bf[8][2]; \
        _Pragma("unroll") \
        for (int nt = 0; nt < 8; nt++) { \
            int n = wn * 64 + nt * 8 + (lane >> 2); \
            bf[nt][0] = Bs[(p0 + (lane & 3)) * BSTR + n]; \
            bf[nt][1] = Bs[(p0 + 4 + (lane & 3)) * BSTR + n]; \
        } \
        _Pragma("unroll") \
        for (int mt = 0; mt < 4; mt++) { \
            int m = wm * 64 + mt * 16 + (lane >> 2); \
            unsigned af[4]; \
            af[0] = As[m * ASTR + p0 + (lane & 3)]; \
            af[1] = As[(m + 8) * ASTR + p0 + (lane & 3)]; \
            af[2] = As[m * ASTR + p0 + 4 + (lane & 3)]; \
            af[3] = As[(m + 8) * ASTR + p0 + 4 + (lane & 3)]; \
            _Pragma("unroll") \
            for (int nt = 0; nt < 8; nt++) mma_f16(acc[mt][nt], af, bf[nt]); \
        } \
    }

// store prefetched regs (pa[8] uint2, pb[4] uint4) into smem (128 threads)
#define GEMM16_STORE_REGS \
    _Pragma("unroll") \
    for (int p = 0; p < 8; p++) \
        *(uint2*)&As[((tid >> 3) + p * 16) * ASTR + (tid & 7) * 2] = pa[p]; \
    _Pragma("unroll") \
    for (int p = 0; p < 4; p++) \
        *(uint4*)&Bs[((tid >> 5) + p * 4) * BSTR + (tid & 31) * 4] = pb[p];

// ---------------- misc helpers ----------------
__device__ __forceinline__ float block_reduce_sum(float v) {
    __shared__ float sh[32];
    int lane = threadIdx.x & 31, w = threadIdx.x >> 5;
    #pragma unroll
    for (int o = 16; o > 0; o >>= 1) v += __shfl_xor_sync(0xffffffffu, v, o);
    if (lane == 0) sh[w] = v;
    __syncthreads();
    if (w == 0) {
        v = (lane < (int)(blockDim.x >> 5)) ? sh[lane] : 0.f;
        #pragma unroll
        for (int o = 16; o > 0; o >>= 1) v += __shfl_xor_sync(0xffffffffu, v, o);
        if (lane == 0) sh[0] = v;
    }
    __syncthreads();
    float r = sh[0];
    __syncthreads();
    return r;
}

__global__ void reset_kernel() {
    int i = blockIdx.x * blockDim.x + threadIdx.x;
    if (i < kSlots) g_slot_token[i] = -1;
    if (i < kE) { g_counts[i] = 0; g_impsum[i] = 0.f; }
}

__global__ void ln_kernel(const float* __restrict__ in, const float* __restrict__ g,
                          const float* __restrict__ b, float* __restrict__ out) {
    int row = blockIdx.x;
    const float* x = in + (size_t)row * kD;
    float s = 0.f;
    for (int i = threadIdx.x; i < kD; i += blockDim.x) s += x[i];
    float mean = block_reduce_sum(s) * (1.f / kD);
    float v = 0.f;
    for (int i = threadIdx.x; i < kD; i += blockDim.x) {
        float d = x[i] - mean; v += d * d;
    }
    float var = block_reduce_sum(v) * (1.f / kD);
    float rstd = rsqrtf(var + 1e-6f);
    float* o = out + (size_t)row * kD;
    for (int i = threadIdx.x; i < kD; i += blockDim.x)
        o[i] = (x[i] - mean) * rstd * g[i] + b[i];
}

// ---------------- QKV fp16 GEMM + fused RoPE (K written transposed) ----------------
__global__ __launch_bounds__(128) void qkv_kernel(
    const float* __restrict__ x,
    const float* __restrict__ WQ, const float* __restrict__ WK, const float* __restrict__ WV,
    float* __restrict__ Qo, float* __restrict__ KTo, float* __restrict__ Vo) {
    GEMM16_SMEM
    int tid = threadIdx.x, lane = tid & 31, w = tid >> 5;
    int wm = w & 1, wn = w >> 1;
    int r0 = blockIdx.x * 128;
    int n0 = blockIdx.y * 128;
    int z = blockIdx.z;
    const float* W = (z == 0) ? WQ : (z == 1) ? WK : WV;

    int bn4 = (tid & 31) * 4;
    int bh = (n0 + bn4) >> 6, be = (n0 + bn4) & 63;
    uint2 pa[8];
    uint4 pb[4];

    #define QKV_LOAD_REGS(k0_) { \
        _Pragma("unroll") \
        for (int p = 0; p < 8; p++) { \
            int m = (tid >> 3) + p * 16; \
            float4 v = *(const float4*)&x[(size_t)(r0 + m) * kD + (k0_) + (tid & 7) * 4]; \
            pa[p].x = pk2(v.x, v.y); pa[p].y = pk2(v.z, v.w); \
        } \
        _Pragma("unroll") \
        for (int p = 0; p < 4; p++) { \
            int kp = (tid >> 5) + p * 4; \
            const float* b0p = &W[((size_t)bh * kD + (k0_) + 2 * kp) * kDH + be]; \
            float4 r0v = *(const float4*)b0p; \
            float4 r1v = *(const float4*)(b0p + kDH); \
            pb[p].x = pk2(r0v.x, r1v.x); pb[p].y = pk2(r0v.y, r1v.y); \
            pb[p].z = pk2(r0v.z, r1v.z); pb[p].w = pk2(r0v.w, r1v.w); \
        } \
    }

    float acc[4][8][4] = {};
    QKV_LOAD_REGS(0)
    GEMM16_STORE_REGS
    __syncthreads();
    for (int k0 = 0; k0 < kD; k0 += 32) {
        if (k0 + 32 < kD) QKV_LOAD_REGS(k0 + 32)
        GEMM16_COMPUTE
        __syncthreads();
        if (k0 + 32 < kD) {
            GEMM16_STORE_REGS
            __syncthreads();
        }
    }
    #undef QKV_LOAD_REGS

    #pragma unroll
    for (int mt = 0; mt < 4; mt++) {
        #pragma unroll
        for (int nt = 0; nt < 8; nt++) {
            int n = n0 + wn * 64 + nt * 8 + (lane & 3) * 2;
            int h = n >> 6, e = n & 63;
            #pragma unroll
            for (int half = 0; half < 2; half++) {
                int t = r0 + wm * 64 + mt * 16 + (lane >> 2) + half * 8;
                float v0 = acc[mt][nt][half * 2 + 0];
                float v1 = acc[mt][nt][half * 2 + 1];
                if (z < 2) {
                    int p = e >> 1;
                    float theta = exp2f(-(float)p * (13.287712379549449f / 32.f));
                    float sn, cs;
                    sincosf((float)t * theta, &sn, &cs);
                    float w0 = v0 * cs - v1 * sn;
                    float w1 = v1 * cs + v0 * sn;
                    v0 = w0; v1 = w1;
                }
                if (z == 1) {
                    KTo[((size_t)h * kDH + e) * kT + t]     = v0;
                    KTo[((size_t)h * kDH + e + 1) * kT + t] = v1;
                } else {
                    float* O = (z == 0) ? Qo : Vo;
                    float2 r2 = { v0, v1 };
                    *(float2*)&O[((size_t)h * kT + t) * kDH + e] = r2;
                }
            }
        }
    }
}

// ---------------- flash attention (tf32 mma): block = (64 q-rows, head), 4 warps ----------------
constexpr int KSTR = 72;
constexpr int PSTR = 68;
constexpr int ATTN_SMEM_BYTES = (64 * PSTR + 2 * 64 * KSTR) * 4;   // 54272

__global__ __launch_bounds__(128) void attn_kernel(
    const float* __restrict__ Q, const float* __restrict__ KTr,
    const float* __restrict__ V, float* __restrict__ A) {
    extern __shared__ __align__(16) unsigned sm_attn[];
    unsigned* QPs = sm_attn;
    unsigned* Ks  = sm_attn + 64 * PSTR;
    unsigned* Vs  = Ks + 64 * KSTR;
    int tid = threadIdx.x, lane = tid & 31, w = tid >> 5;
    int h = blockIdx.y;
    int qt = (int)gridDim.x - 1 - (int)blockIdx.x;
    int q0 = qt * 64;
    const float* Qh  = Q   + ((size_t)h * kT + q0) * kDH;
    const float* KTh = KTr + (size_t)h * kDH * kT;
    const float* Vh  = V   + (size_t)h * kT * kDH;

    #pragma unroll
    for (int it = 0; it < 8; it++) {
        int idx = tid + it * 128;
        int m = idx >> 4, dh4 = (idx & 15) * 4;
        float4 v = *(const float4*)&Qh[(size_t)m * kDH + dh4];
        uint4 u = { f2tf32(v.x), f2tf32(v.y), f2tf32(v.z), f2tf32(v.w) };
        *(uint4*)&QPs[m * PSTR + dh4] = u;
    }
    __syncthreads();
    unsigned qf[8][4];
    {
        int m = w * 16 + (lane >> 2);
        #pragma unroll
        for (int kk = 0; kk < 8; kk++) {
            qf[kk][0] = QPs[m * PSTR + kk * 8 + (lane & 3)];
            qf[kk][1] = QPs[(m + 8) * PSTR + kk * 8 + (lane & 3)];
            qf[kk][2] = QPs[m * PSTR + kk * 8 + 4 + (lane & 3)];
            qf[kk][3] = QPs[(m + 8) * PSTR + kk * 8 + 4 + (lane & 3)];
        }
    }

    float acc_o[8][4] = {};
    float m0 = -1e30f, m1 = -1e30f, l0 = 0.f, l1 = 0.f;

    for (int kt = 0; kt <= qt; kt++) {
        int k0 = kt * 64;
        __syncthreads();
        #pragma unroll
        for (int it = 0; it < 8; it++) {
            int idx = tid + it * 128;
            int dh = idx >> 4, key4 = (idx & 15) * 4;
            float4 v = *(const float4*)&KTh[(size_t)dh * kT + k0 + key4];
            uint4 u = { f2tf32(v.x), f2tf32(v.y), f2tf32(v.z), f2tf32(v.w) };
            *(uint4*)&Ks[dh * KSTR + key4] = u;
        }
        #pragma unroll
        for (int it = 0; it < 8; it++) {
            int idx = tid + it * 128;
            int key = idx >> 4, dh4 = (idx & 15) * 4;
            float4 v = *(const float4*)&Vh[(size_t)(k0 + key) * kDH + dh4];
            uint4 u = { f2tf32(v.x), f2tf32(v.y), f2tf32(v.z), f2tf32(v.w) };
            *(uint4*)&Vs[key * KSTR + dh4] = u;
        }
        __syncthreads();

        float s_acc[8][4] = {};
        #pragma unroll
        for (int kk = 0; kk < 8; kk++) {
            #pragma unroll
            for (int nt = 0; nt < 8; nt++) {
                unsigned bf[2];
                bf[0] = Ks[(kk * 8 + (lane & 3)) * KSTR + nt * 8 + (lane >> 2)];
                bf[1] = Ks[(kk * 8 + 4 + (lane & 3)) * KSTR + nt * 8 + (lane >> 2)];
                mma_tf32(s_acc[nt], qf[kk], bf);
            }
        }

        float rm0 = -1e30f, rm1 = -1e30f;
        int gq0 = q0 + w * 16 + (lane >> 2);
        #pragma unroll
        for (int nt = 0; nt < 8; nt++) {
            #pragma unroll
            for (int c = 0; c < 4; c++) {
                float v = s_acc[nt][c] * 0.125f;
                if (kt == qt) {
                    int key = k0 + nt * 8 + 2 * (lane & 3) + (c & 1);
                    int gq = gq0 + (c >> 1) * 8;
                    if (key > gq) v = -1e30f;
                }
                s_acc[nt][c] = v;
                if ((c >> 1) == 0) rm0 = fmaxf(rm0, v); else rm1 = fmaxf(rm1, v);
            }
        }
        #pragma unroll
        for (int o = 1; o <= 2; o <<= 1) {
            rm0 = fmaxf(rm0, __shfl_xor_sync(0xffffffffu, rm0, o));
            rm1 = fmaxf(rm1, __shfl_xor_sync(0xffffffffu, rm1, o));
        }
        float nm0 = fmaxf(m0, rm0), nm1 = fmaxf(m1, rm1);
        float sc0 = __expf(m0 - nm0), sc1 = __expf(m1 - nm1);
        m0 = nm0; m1 = nm1;

        float rs0 = 0.f, rs1 = 0.f;
        int prow = w * 16 + (lane >> 2);
        #pragma unroll
        for (int nt = 0; nt < 8; nt++) {
            float p0 = __expf(s_acc[nt][0] - nm0);
            float p1 = __expf(s_acc[nt][1] - nm0);
            float p2 = __expf(s_acc[nt][2] - nm1);
            float p3 = __expf(s_acc[nt][3] - nm1);
            rs0 += p0 + p1; rs1 += p2 + p3;
            uint2 u01 = { f2tf32(p0), f2tf32(p1) };
            uint2 u23 = { f2tf32(p2), f2tf32(p3) };
            *(uint2*)&QPs[prow * PSTR + nt * 8 + 2 * (lane & 3)] = u01;
            *(uint2*)&QPs[(prow + 8) * PSTR + nt * 8 + 2 * (lane & 3)] = u23;
        }
        #pragma unroll
        for (int o = 1; o <= 2; o <<= 1) {
            rs0 += __shfl_xor_sync(0xffffffffu, rs0, o);
            rs1 += __shfl_xor_sync(0xffffffffu, rs1, o);
        }
        l0 = l0 * sc0 + rs0;
        l1 = l1 * sc1 + rs1;
        #pragma unroll
        for (int nt = 0; nt < 8; nt++) {
            acc_o[nt][0] *= sc0; acc_o[nt][1] *= sc0;
            acc_o[nt][2] *= sc1; acc_o[nt][3] *= sc1;
        }
        __syncwarp();

        #pragma unroll
        for (int kk = 0; kk < 8; kk++) {
            unsigned pf[4];
            int m = w * 16 + (lane >> 2);
            pf[0] = QPs[m * PSTR + kk * 8 + (lane & 3)];
            pf[1] = QPs[(m + 8) * PSTR + kk * 8 + (lane & 3)];
            pf[2] = QPs[m * PSTR + kk * 8 + 4 + (lane & 3)];
            pf[3] = QPs[(m + 8) * PSTR + kk * 8 + 4 + (lane & 3)];
            #pragma unroll
            for (int nt = 0; nt < 8; nt++) {
                unsigned bf[2];
                bf[0] = Vs[(kk * 8 + (lane & 3)) * KSTR + nt * 8 + (lane >> 2)];
                bf[1] = Vs[(kk * 8 + 4 + (lane & 3)) * KSTR + nt * 8 + (lane >> 2)];
                mma_tf32(acc_o[nt], pf, bf);
            }
        }
    }

    float inv0 = 1.f / l0, inv1 = 1.f / l1;
    int gq0 = q0 + w * 16 + (lane >> 2);
    #pragma unroll
    for (int nt = 0; nt < 8; nt++) {
        int col = h * kDH + nt * 8 + 2 * (lane & 3);
        float2 r0 = { acc_o[nt][0] * inv0, acc_o[nt][1] * inv0 };
        float2 r1 = { acc_o[nt][2] * inv1, acc_o[nt][3] * inv1 };
        *(float2*)&A[(size_t)gq0 * kD + col] = r0;
        *(float2*)&A[(size_t)(gq0 + 8) * kD + col] = r1;
    }
}

// ---------------- proj fp16 GEMM + residual ----------------
__global__ __launch_bounds__(128) void proj_kernel(
    const float* __restrict__ A, const float* __restrict__ W,
    const float* __restrict__ bias, const float* __restrict__ emb,
    float* __restrict__ out) {
    GEMM16_SMEM
    int tid = threadIdx.x, lane = tid & 31, w = tid >> 5;
    int wm = w & 1, wn = w >> 1;
    int r0 = blockIdx.x * 128;
    int n0 = blockIdx.y * 128;

    uint2 pa[8];
    uint4 pb[4];

    #define PROJ_LOAD_REGS(k0_) { \
        _Pragma("unroll") \
        for (int p = 0; p < 8; p++) { \
            int m = (tid >> 3) + p * 16; \
            float4 v = *(const float4*)&A[(size_t)(r0 + m) * kD + (k0_) + (tid & 7) * 4]; \
            pa[p].x = pk2(v.x, v.y); pa[p].y = pk2(v.z, v.w); \
        } \
        _Pragma("unroll") \
        for (int p = 0; p < 4; p++) { \
            int kp = (tid >> 5) + p * 4; \
            const float* b0p = &W[(size_t)((k0_) + 2 * kp) * kD + n0 + (tid & 31) * 4]; \
            float4 r0v = *(const float4*)b0p; \
            float4 r1v = *(const float4*)(b0p + kD); \
            pb[p].x = pk2(r0v.x, r1v.x); pb[p].y = pk2(r0v.y, r1v.y); \
            pb[p].z = pk2(r0v.z, r1v.z); pb[p].w = pk2(r0v.w, r1v.w); \
        } \
    }

    float acc[4][8][4] = {};
    PROJ_LOAD_REGS(0)
    GEMM16_STORE_REGS
    __syncthreads();
    for (int k0 = 0; k0 < kD; k0 += 32) {
        if (k0 + 32 < kD) PROJ_LOAD_REGS(k0 + 32)
        GEMM16_COMPUTE
        __syncthreads();
        if (k0 + 32 < kD) {
            GEMM16_STORE_REGS
            __syncthreads();
        }
    }
    #undef PROJ_LOAD_REGS

    #pragma unroll
    for (int mt = 0; mt < 4; mt++) {
        #pragma unroll
        for (int nt = 0; nt < 8; nt++) {
            int c = n0 + wn * 64 + nt * 8 + (lane & 3) * 2;
            #pragma unroll
            for (int half = 0; half < 2; half++) {
                int r = r0 + wm * 64 + mt * 16 + (lane >> 2) + half * 8;
                float2 e2 = *(const float2*)&emb[(size_t)r * kD + c];
                float2 r2;
                r2.x = e2.x + acc[mt][nt][half * 2 + 0] + bias[c];
                r2.y = e2.y + acc[mt][nt][half * 2 + 1] + bias[c + 1];
                *(float2*)&out[(size_t)r * kD + c] = r2;
            }
        }
    }
}

// ---------------- router ----------------
__global__ void router_kernel(const float* __restrict__ y, const float* __restrict__ Wr,
                              const float* __restrict__ br) {
    int warp = (blockIdx.x * blockDim.x + threadIdx.x) >> 5;
    int lane = threadIdx.x & 31;
    if (warp >= kT) return;
    const float* yr = y + (size_t)warp * kD;
    float s[kE];
    #pragma unroll
    for (int e = 0; e < kE; e++) s[e] = 0.f;
    for (int d = lane; d < kD; d += 32) {
        float yv = yr[d];
        const float* wr = Wr + (size_t)d * kE;
        #pragma unroll
        for (int e = 0; e < kE; e++) s[e] += yv * wr[e];
    }
    #pragma unroll
    for (int e = 0; e < kE; e++) {
        float v = s[e];
        #pragma unroll
        for (int o = 16; o > 0; o >>= 1) v += __shfl_xor_sync(0xffffffffu, v, o);
        s[e] = v;
    }
    if (lane == 0) {
        float w[kE];
        float mx = -1e30f;
        #pragma unroll
        for (int e = 0; e < kE; e++) { w[e] = s[e] + br[e]; mx = fmaxf(mx, w[e]); }
        float sum = 0.f;
        #pragma unroll
        for (int e = 0; e < kE; e++) { w[e] = __expf(w[e] - mx); sum += w[e]; }
        float inv = 1.f / sum;
        #pragma unroll
        for (int e = 0; e < kE; e++) w[e] *= inv;
        int i0 = 0;
        #pragma unroll
        for (int e = 1; e < kE; e++) if (w[e] > w[i0]) i0 = e;
        int i1 = -1;
        #pragma unroll
        for (int e = 0; e < kE; e++) if (e != i0 && (i1 < 0 || w[e] > w[i1])) i1 = e;
        float norm = w[i0] + w[i1];
        g_ids[warp * 2]     = i0;
        g_ids[warp * 2 + 1] = i1;
        g_gates[warp * 2]     = w[i0] / norm;
        g_gates[warp * 2 + 1] = w[i1] / norm;
        atomicAdd(&g_counts[i0], 1);
        atomicAdd(&g_counts[i1], 1);
        #pragma unroll
        for (int e = 0; e < kE; e++) atomicAdd(&g_impsum[e], w[e]);
    }
}

__global__ void offsets_kernel(float* __restrict__ out, int out_size) {
    if (threadIdx.x == 0 && blockIdx.x == 0) {
        int off = 0;
        g_poff[0] = 0;
        for (int e = 0; e < kE; e++) {
            int pc = (g_counts[e] + 127) & ~127;
            off += pc;
            g_poff[e + 1] = off;
            g_cursor[e] = g_poff[e];
        }
        float aux = 0.f;
        for (int e = 0; e < kE; e++) {
            float imp = g_impsum[e] / (float)kT;
            float dlt = imp - 1.f / (float)kE;
            aux += dlt * dlt;
        }
        aux *= 1.f / (float)kE;
        if (out_size > kT * kD) out[kT * kD] = aux;
    }
}

__global__ void scatter_kernel() {
    int i = blockIdx.x * blockDim.x + threadIdx.x;
    if (i >= kT * 2) return;
    int e = g_ids[i];
    int pos = atomicAdd(&g_cursor[e], 1);
    g_slot_token[pos] = i >> 1;
    g_slotpos[i] = pos;
}

// ---------------- F1 fp16 GEMM: h = relu(y_gathered @ W1[e] + b1[e]) ----------------
__global__ __launch_bounds__(128) void f1_kernel(
    const float* __restrict__ y, const float* __restrict__ W1,
    const float* __restrict__ b1) {
    GEMM16_SMEM
    __shared__ int tok[128];
    __shared__ int sh_total, sh_e;
    int tid = threadIdx.x, lane = tid & 31, w = tid >> 5;
    int wm = w & 1, wn = w >> 1;
    int s0 = blockIdx.x * 128;
    if (tid == 0) {
        sh_total = g_poff[kE];
        int e = 0;
        while (e < kE - 1 && s0 >= g_poff[e + 1]) e++;
        sh_e = e;
    }
    tok[tid] = g_slot_token[s0 + tid];
    __syncthreads();
    if (s0 >= sh_total) return;
    int e = sh_e;
    const float* W = W1 + (size_t)e * kD * kDFF;
    int f0 = blockIdx.y * 128;
    int atok[8];
    #pragma unroll
    for (int p = 0; p < 8; p++) atok[p] = tok[(tid >> 3) + p * 16];

    uint2 pa[8];
    uint4 pb[4];

    #define F1_LOAD_REGS(k0_) { \
        _Pragma("unroll") \
        for (int p = 0; p < 8; p++) { \
            int t = atok[p]; \
            if (t >= 0) { \
                float4 v = *(const float4*)&y[(size_t)t * kD + (k0_) + (tid & 7) * 4]; \
                pa[p].x = pk2(v.x, v.y); pa[p].y = pk2(v.z, v.w); \
            } else { pa[p].x = 0u; pa[p].y = 0u; } \
        } \
        _Pragma("unroll") \
        for (int p = 0; p < 4; p++) { \
            int kp = (tid >> 5) + p * 4; \
            const float* b0p = &W[(size_t)((k0_) + 2 * kp) * kDFF + f0 + (tid & 31) * 4]; \
            float4 r0v = *(const float4*)b0p; \
            float4 r1v = *(const float4*)(b0p + kDFF); \
            pb[p].x = pk2(r0v.x, r1v.x); pb[p].y = pk2(r0v.y, r1v.y); \
            pb[p].z = pk2(r0v.z, r1v.z); pb[p].w = pk2(r0v.w, r1v.w); \
        } \
    }

    float acc[4][8][4] = {};
    F1_LOAD_REGS(0)
    GEMM16_STORE_REGS
    __syncthreads();
    for (int k0 = 0; k0 < kD; k0 += 32) {
        if (k0 + 32 < kD) F1_LOAD_REGS(k0 + 32)
        GEMM16_COMPUTE
        __syncthreads();
        if (k0 + 32 < kD) {
            GEMM16_STORE_REGS
            __syncthreads();
        }
    }
    #undef F1_LOAD_REGS

    #pragma unroll
    for (int mt = 0; mt < 4; mt++) {
        #pragma unroll
        for (int nt = 0; nt < 8; nt++) {
            int c = f0 + wn * 64 + nt * 8 + (lane & 3) * 2;
            float bb0 = b1[(size_t)e * kDFF + c];
            float bb1 = b1[(size_t)e * kDFF + c + 1];
            #pragma unroll
            for (int half = 0; half < 2; half++) {
                int r = s0 + wm * 64 + mt * 16 + (lane >> 2) + half * 8;
                float2 r2;
                r2.x = fmaxf(acc[mt][nt][half * 2 + 0] + bb0, 0.f);
                r2.y = fmaxf(acc[mt][nt][half * 2 + 1] + bb1, 0.f);
                *(float2*)&g_h[(size_t)r * kDFF + c] = r2;
            }
        }
    }
}

// ---------------- F2 fp16 GEMM: yo = h @ W2[e] + b2[e] ----------------
__global__ __launch_bounds__(128) void f2_kernel(
    const float* __restrict__ W2, const float* __restrict__ b2) {
    GEMM16_SMEM
    __shared__ int sh_total, sh_e;
    int tid = threadIdx.x, lane = tid & 31, w = tid >> 5;
    int wm = w & 1, wn = w >> 1;
    int s0 = blockIdx.x * 128;
    if (tid == 0) {
        sh_total = g_poff[kE];
        int e = 0;
        while (e < kE - 1 && s0 >= g_poff[e + 1]) e++;
        sh_e = e;
    }
    __syncthreads();
    if (s0 >= sh_total) return;
    int e = sh_e;
    const float* W = W2 + (size_t)e * kDFF * kD;
    int c0 = blockIdx.y * 128;

    uint2 pa[8];
    uint4 pb[4];

    #define F2_LOAD_REGS(k0_) { \
        _Pragma("unroll") \
        for (int p = 0; p < 8; p++) { \
            int m = (tid >> 3) + p * 16; \
            float4 v = *(const float4*)&g_h[(size_t)(s0 + m) * kDFF + (k0_) + (tid & 7) * 4]; \
            pa[p].x = pk2(v.x, v.y); pa[p].y = pk2(v.z, v.w); \
        } \
        _Pragma("unroll") \
        for (int p = 0; p < 4; p++) { \
            int kp = (tid >> 5) + p * 4; \
            const float* b0p = &W[(size_t)((k0_) + 2 * kp) * kD + c0 + (tid & 31) * 4]; \
            float4 r0v = *(const float4*)b0p; \
            float4 r1v = *(const float4*)(b0p + kD); \
            pb[p].x = pk2(r0v.x, r1v.x); pb[p].y = pk2(r0v.y, r1v.y); \
            pb[p].z = pk2(r0v.z, r1v.z); pb[p].w = pk2(r0v.w, r1v.w); \
        } \
    }

    float acc[4][8][4] = {};
    F2_LOAD_REGS(0)
    GEMM16_STORE_REGS
    __syncthreads();
    for (int k0 = 0; k0 < kDFF; k0 += 32) {
        if (k0 + 32 < kDFF) F2_LOAD_REGS(k0 + 32)
        GEMM16_COMPUTE
        __syncthreads();
        if (k0 + 32 < kDFF) {
            GEMM16_STORE_REGS
            __syncthreads();
        }
    }
    #undef F2_LOAD_REGS

    #pragma unroll
    for (int mt = 0; mt < 4; mt++) {
        #pragma unroll
        for (int nt = 0; nt < 8; nt++) {
            int c = c0 + wn * 64 + nt * 8 + (lane & 3) * 2;
            float bb0 = b2[(size_t)e * kD + c];
            float bb1 = b2[(size_t)e * kD + c + 1];
            #pragma unroll
            for (int half = 0; half < 2; half++) {
                int r = s0 + wm * 64 + mt * 16 + (lane >> 2) + half * 8;
                float2 r2;
                r2.x = acc[mt][nt][half * 2 + 0] + bb0;
                r2.y = acc[mt][nt][half * 2 + 1] + bb1;
                *(float2*)&g_yo[(size_t)r * kD + c] = r2;
            }
        }
    }
}

// ---------------- combine ----------------
__global__ void combine_kernel(float* __restrict__ out) {
    int idx4 = blockIdx.x * blockDim.x + threadIdx.x;
    if (idx4 >= kT * kD / 4) return;
    int idx = idx4 * 4;
    int n = idx >> 10;
    int d = idx & (kD - 1);
    int p0 = g_slotpos[n * 2], p1 = g_slotpos[n * 2 + 1];
    float g0 = g_gates[n * 2], g1 = g_gates[n * 2 + 1];
    float4 base = *(const float4*)&g_emb2[idx];
    float4 y0 = *(const float4*)&g_yo[(size_t)p0 * kD + d];
    float4 y1 = *(const float4*)&g_yo[(size_t)p1 * kD + d];
    float4 r;
    r.x = base.x + g0 * y0.x + g1 * y1.x;
    r.y = base.y + g0 * y0.y + g1 * y1.y;
    r.z = base.z + g0 * y0.z + g1 * y1.z;
    r.w = base.w + g0 * y0.w + g1 * y1.w;
    *(float4*)&out[idx] = r;
}

// ---------------- launch ----------------
extern "C" void kernel_launch(void* const* d_in, const int* in_sizes, int n_in,
                              void* d_out, int out_size) {
    const float* emb    = (const float*)d_in[0];
    const float* gamma1 = (const float*)d_in[1];
    const float* beta1  = (const float*)d_in[2];
    const float* WQ     = (const float*)d_in[3];
    const float* WK     = (const float*)d_in[4];
    const float* WV     = (const float*)d_in[5];
    const float* Wproj  = (const float*)d_in[6];
    const float* bproj  = (const float*)d_in[7];
    const float* gamma2 = (const float*)d_in[8];
    const float* beta2  = (const float*)d_in[9];
    const float* Wr     = (const float*)d_in[10];
    const float* br     = (const float*)d_in[11];
    const float* W1     = (const float*)d_in[12];
    const float* b1     = (const float*)d_in[13];
    const float* W2     = (const float*)d_in[14];
    const float* b2     = (const float*)d_in[15];
    float* out = (float*)d_out;

    float* gx;    cudaGetSymbolAddress((void**)&gx, g_x);
    float* gq;    cudaGetSymbolAddress((void**)&gq, g_q);
    float* gkT;   cudaGetSymbolAddress((void**)&gkT, g_kT);
    float* gv;    cudaGetSymbolAddress((void**)&gv, g_v);
    float* gattn; cudaGetSymbolAddress((void**)&gattn, g_attn);
    float* gemb2; cudaGetSymbolAddress((void**)&gemb2, g_emb2);
    float* gy;    cudaGetSymbolAddress((void**)&gy, g_y);

    cudaFuncSetAttribute(attn_kernel, cudaFuncAttributeMaxDynamicSharedMemorySize,
                         ATTN_SMEM_BYTES);

    reset_kernel<<<(kSlots + 255) / 256, 256>>>();
    ln_kernel<<<kT, 256>>>(emb, gamma1, beta1, gx);
    qkv_kernel<<<dim3(kT / 128, (kH * kDH) / 128, 3), 128>>>(gx, WQ, WK, WV, gq, gkT, gv);
    attn_kernel<<<dim3(kT / 64, kH), 128, ATTN_SMEM_BYTES>>>(gq, gkT, gv, gattn);
    proj_kernel<<<dim3(kT / 128, kD / 128), 128>>>(gattn, Wproj, bproj, emb, gemb2);
    ln_kernel<<<kT, 256>>>(gemb2, gamma2, beta2, gy);
    router_kernel<<<kT / 8, 256>>>(gy, Wr, br);
    offsets_kernel<<<1, 32>>>(out, out_size);
    scatter_kernel<<<(kT * 2 + 255) / 256, 256>>>();
    f1_kernel<<<dim3(kSlots / 128, kDFF / 128), 128>>>(gy, W1, b1);
    f2_kernel<<<dim3(kSlots / 128, kD / 128), 128>>>(W2, b2);
    combine_kernel<<<(kT * kD / 4 + 255) / 256, 256>>>(out);
}

// round 11
// speedup vs baseline: 1.0994x; 1.0994x over previous
#include <cuda_runtime.h>
#include <cuda_fp16.h>
#include <math.h>

// ---------------- problem constants ----------------
constexpr int kT   = 1024;
constexpr int kD   = 1024;
constexpr int kH   = 16;
constexpr int kDH  = 64;
constexpr int kE   = 8;
constexpr int kDFF = 4096;
constexpr int kSlots = 3072;   // 2048 assignments + per-expert pad to 128

// ---------------- device scratch ----------------
__device__ float g_x[kT * kD];
__device__ float g_q[kH * kT * kDH];
__device__ float g_kT[kH * kDH * kT];   // K transposed: [h][dh][t]
__device__ float g_v[kH * kT * kDH];
__device__ float g_attn[kT * kD];
__device__ float g_emb2[kT * kD];
__device__ float g_y[kT * kD];
__device__ __half g_h[kSlots * kDFF];   // expert hidden, fp16 (bit-identical to f2's pk2)
__device__ float g_yo[kSlots * kD];
__device__ int   g_ids[kT * 2];
__device__ float g_gates[kT * 2];
__device__ int   g_counts[kE];
__device__ int   g_poff[kE + 1];
__device__ int   g_cursor[kE];
__device__ int   g_slot_token[kSlots];
__device__ int   g_slotpos[kT * 2];
__device__ float g_impsum[kE];

// ---------------- mma helpers ----------------
__device__ __forceinline__ unsigned f2tf32(float x) {
    unsigned y; asm("cvt.rna.tf32.f32 %0, %1;" : "=r"(y) : "f"(x)); return y;
}
__device__ __forceinline__ void mma_tf32(float c[4], const unsigned a[4], const unsigned b[2]) {
    asm volatile("mma.sync.aligned.m16n8k8.row.col.f32.tf32.tf32.f32 "
        "{%0,%1,%2,%3}, {%4,%5,%6,%7}, {%8,%9}, {%0,%1,%2,%3};\n"
        : "+f"(c[0]), "+f"(c[1]), "+f"(c[2]), "+f"(c[3])
        : "r"(a[0]), "r"(a[1]), "r"(a[2]), "r"(a[3]), "r"(b[0]), "r"(b[1]));
}
__device__ __forceinline__ void mma_f16(float c[4], const unsigned a[4], const unsigned b[2]) {
    asm volatile("mma.sync.aligned.m16n8k16.row.col.f32.f16.f16.f32 "
        "{%0,%1,%2,%3}, {%4,%5,%6,%7}, {%8,%9}, {%0,%1,%2,%3};\n"
        : "+f"(c[0]), "+f"(c[1]), "+f"(c[2]), "+f"(c[3])
        : "r"(a[0]), "r"(a[1]), "r"(a[2]), "r"(a[3]), "r"(b[0]), "r"(b[1]));
}
__device__ __forceinline__ unsigned pk2(float a, float b) {
    __half2 h = __floats2half2_rn(a, b);
    return *(unsigned*)&h;
}

// fp16 GEMM tile config: block 256 threads, tile M=128 N=128, warp tile 32x64,
// K-panel 32 (= 2 k16 MMAs).
constexpr int ASTR = 20;
constexpr int BSTR = 136;

#define GEMM16_SMEM \
    __shared__ __align__(16) unsigned As[128 * ASTR]; \
    __shared__ __align__(16) unsigned Bs[16 * BSTR];

// compute one 32-deep panel: 2 k16 steps (pair offsets p0 = 0, 8)
#define GEMM16_COMPUTE \
    _Pragma("unroll") \
    for (int p0 = 0; p0 < 16; p0 += 8) { \
        unsigned bf[8][2]; \
        _Pragma("unroll") \
        for (int nt = 0; nt < 8; nt++) { \
            int n = wn * 64 + nt * 8 + (lane >> 2); \
            bf[nt][0] = Bs[(p0 + (lane & 3)) * BSTR + n]; \
            bf[nt][1] = Bs[(p0 + 4 + (lane & 3)) * BSTR + n]; \
        } \
        _Pragma("unroll") \
        for (int mt = 0; mt < 2; mt++) { \
            int m = wm * 32 + mt * 16 + (lane >> 2); \
            unsigned af[4]; \
            af[0] = As[m * ASTR + p0 + (lane & 3)]; \
            af[1] = As[(m + 8) * ASTR + p0 + (lane & 3)]; \
            af[2] = As[m * ASTR + p0 + 4 + (lane & 3)]; \
            af[3] = As[(m + 8) * ASTR + p0 + 4 + (lane & 3)]; \
            _Pragma("unroll") \
            for (int nt = 0; nt < 8; nt++) mma_f16(acc[mt][nt], af, bf[nt]); \
        } \
    }

// store prefetched regs (pa[4] uint2, pb[2] uint4) into smem (256 threads)
#define GEMM16_STORE_REGS \
    _Pragma("unroll") \
    for (int p = 0; p < 4; p++) \
        *(uint2*)&As[((tid >> 3) + p * 32) * ASTR + (tid & 7) * 2] = pa[p]; \
    _Pragma("unroll") \
    for (int p = 0; p < 2; p++) \
        *(uint4*)&Bs[((tid >> 5) + p * 8) * BSTR + (tid & 31) * 4] = pb[p];

// ---------------- misc helpers ----------------
__device__ __forceinline__ float block_reduce_sum(float v) {
    __shared__ float sh[32];
    int lane = threadIdx.x & 31, w = threadIdx.x >> 5;
    #pragma unroll
    for (int o = 16; o > 0; o >>= 1) v += __shfl_xor_sync(0xffffffffu, v, o);
    if (lane == 0) sh[w] = v;
    __syncthreads();
    if (w == 0) {
        v = (lane < (int)(blockDim.x >> 5)) ? sh[lane] : 0.f;
        #pragma unroll
        for (int o = 16; o > 0; o >>= 1) v += __shfl_xor_sync(0xffffffffu, v, o);
        if (lane == 0) sh[0] = v;
    }
    __syncthreads();
    float r = sh[0];
    __syncthreads();
    return r;
}

__global__ void reset_kernel() {
    int i = blockIdx.x * blockDim.x + threadIdx.x;
    if (i < kSlots) g_slot_token[i] = -1;
    if (i < kE) { g_counts[i] = 0; g_impsum[i] = 0.f; }
}

__global__ void ln_kernel(const float* __restrict__ in, const float* __restrict__ g,
                          const float* __restrict__ b, float* __restrict__ out) {
    int row = blockIdx.x;
    const float* x = in + (size_t)row * kD;
    float s = 0.f;
    for (int i = threadIdx.x; i < kD; i += blockDim.x) s += x[i];
    float mean = block_reduce_sum(s) * (1.f / kD);
    float v = 0.f;
    for (int i = threadIdx.x; i < kD; i += blockDim.x) {
        float d = x[i] - mean; v += d * d;
    }
    float var = block_reduce_sum(v) * (1.f / kD);
    float rstd = rsqrtf(var + 1e-6f);
    float* o = out + (size_t)row * kD;
    for (int i = threadIdx.x; i < kD; i += blockDim.x)
        o[i] = (x[i] - mean) * rstd * g[i] + b[i];
}

// ---------------- fused LN2 + router: block per token row ----------------
__global__ void ln2_router_kernel(const float* __restrict__ in,
                                  const float* __restrict__ g, const float* __restrict__ b,
                                  float* __restrict__ out,
                                  const float* __restrict__ Wr, const float* __restrict__ br) {
    int row = blockIdx.x;
    const float* x = in + (size_t)row * kD;
    float s = 0.f;
    for (int i = threadIdx.x; i < kD; i += blockDim.x) s += x[i];
    float mean = block_reduce_sum(s) * (1.f / kD);
    float v = 0.f;
    for (int i = threadIdx.x; i < kD; i += blockDim.x) {
        float d = x[i] - mean; v += d * d;
    }
    float var = block_reduce_sum(v) * (1.f / kD);
    float rstd = rsqrtf(var + 1e-6f);
    float* o = out + (size_t)row * kD;
    float rs[kE];
    #pragma unroll
    for (int e = 0; e < kE; e++) rs[e] = 0.f;
    for (int i = threadIdx.x; i < kD; i += blockDim.x) {
        float val = (x[i] - mean) * rstd * g[i] + b[i];
        o[i] = val;
        const float* wr = Wr + (size_t)i * kE;
        #pragma unroll
        for (int e = 0; e < kE; e++) rs[e] += val * wr[e];
    }
    #pragma unroll
    for (int e = 0; e < kE; e++) rs[e] = block_reduce_sum(rs[e]);
    if (threadIdx.x == 0) {
        float w[kE];
        float mx = -1e30f;
        #pragma unroll
        for (int e = 0; e < kE; e++) { w[e] = rs[e] + br[e]; mx = fmaxf(mx, w[e]); }
        float sum = 0.f;
        #pragma unroll
        for (int e = 0; e < kE; e++) { w[e] = __expf(w[e] - mx); sum += w[e]; }
        float inv = 1.f / sum;
        #pragma unroll
        for (int e = 0; e < kE; e++) w[e] *= inv;
        int i0 = 0;
        #pragma unroll
        for (int e = 1; e < kE; e++) if (w[e] > w[i0]) i0 = e;
        int i1 = -1;
        #pragma unroll
        for (int e = 0; e < kE; e++) if (e != i0 && (i1 < 0 || w[e] > w[i1])) i1 = e;
        float norm = w[i0] + w[i1];
        g_ids[row * 2]     = i0;
        g_ids[row * 2 + 1] = i1;
        g_gates[row * 2]     = w[i0] / norm;
        g_gates[row * 2 + 1] = w[i1] / norm;
        atomicAdd(&g_counts[i0], 1);
        atomicAdd(&g_counts[i1], 1);
        #pragma unroll
        for (int e = 0; e < kE; e++) atomicAdd(&g_impsum[e], w[e]);
    }
}

// ---------------- QKV fp16 GEMM + fused RoPE (K written transposed) ----------------
__global__ __launch_bounds__(256) void qkv_kernel(
    const float* __restrict__ x,
    const float* __restrict__ WQ, const float* __restrict__ WK, const float* __restrict__ WV,
    float* __restrict__ Qo, float* __restrict__ KTo, float* __restrict__ Vo) {
    GEMM16_SMEM
    int tid = threadIdx.x, lane = tid & 31, w = tid >> 5;
    int wm = w & 3, wn = w >> 2;
    int r0 = blockIdx.x * 128;
    int n0 = blockIdx.y * 128;
    int z = blockIdx.z;
    const float* W = (z == 0) ? WQ : (z == 1) ? WK : WV;

    int bn4 = (tid & 31) * 4;
    int bh = (n0 + bn4) >> 6, be = (n0 + bn4) & 63;
    uint2 pa[4];
    uint4 pb[2];

    #define QKV_LOAD_REGS(k0_) { \
        _Pragma("unroll") \
        for (int p = 0; p < 4; p++) { \
            int m = (tid >> 3) + p * 32; \
            float4 v = *(const float4*)&x[(size_t)(r0 + m) * kD + (k0_) + (tid & 7) * 4]; \
            pa[p].x = pk2(v.x, v.y); pa[p].y = pk2(v.z, v.w); \
        } \
        _Pragma("unroll") \
        for (int p = 0; p < 2; p++) { \
            int kp = (tid >> 5) + p * 8; \
            const float* b0p = &W[((size_t)bh * kD + (k0_) + 2 * kp) * kDH + be]; \
            float4 r0v = *(const float4*)b0p; \
            float4 r1v = *(const float4*)(b0p + kDH); \
            pb[p].x = pk2(r0v.x, r1v.x); pb[p].y = pk2(r0v.y, r1v.y); \
            pb[p].z = pk2(r0v.z, r1v.z); pb[p].w = pk2(r0v.w, r1v.w); \
        } \
    }

    float acc[2][8][4] = {};
    QKV_LOAD_REGS(0)
    GEMM16_STORE_REGS
    __syncthreads();
    for (int k0 = 0; k0 < kD; k0 += 32) {
        if (k0 + 32 < kD) QKV_LOAD_REGS(k0 + 32)
        GEMM16_COMPUTE
        __syncthreads();
        if (k0 + 32 < kD) {
            GEMM16_STORE_REGS
            __syncthreads();
        }
    }
    #undef QKV_LOAD_REGS

    #pragma unroll
    for (int mt = 0; mt < 2; mt++) {
        #pragma unroll
        for (int nt = 0; nt < 8; nt++) {
            int n = n0 + wn * 64 + nt * 8 + (lane & 3) * 2;
            int h = n >> 6, e = n & 63;
            #pragma unroll
            for (int half = 0; half < 2; half++) {
                int t = r0 + wm * 32 + mt * 16 + (lane >> 2) + half * 8;
                float v0 = acc[mt][nt][half * 2 + 0];
                float v1 = acc[mt][nt][half * 2 + 1];
                if (z < 2) {
                    int p = e >> 1;
                    float theta = exp2f(-(float)p * (13.287712379549449f / 32.f));
                    float sn, cs;
                    sincosf((float)t * theta, &sn, &cs);
                    float w0 = v0 * cs - v1 * sn;
                    float w1 = v1 * cs + v0 * sn;
                    v0 = w0; v1 = w1;
                }
                if (z == 1) {
                    KTo[((size_t)h * kDH + e) * kT + t]     = v0;
                    KTo[((size_t)h * kDH + e + 1) * kT + t] = v1;
                } else {
                    float* O = (z == 0) ? Qo : Vo;
                    float2 r2 = { v0, v1 };
                    *(float2*)&O[((size_t)h * kT + t) * kDH + e] = r2;
                }
            }
        }
    }
}

// ---------------- flash attention (tf32 mma): block = (64 q-rows, head), 4 warps ----------------
constexpr int KSTR = 72;
constexpr int PSTR = 68;
constexpr int ATTN_SMEM_BYTES = (64 * PSTR + 2 * 64 * KSTR) * 4;   // 54272

__global__ __launch_bounds__(128) void attn_kernel(
    const float* __restrict__ Q, const float* __restrict__ KTr,
    const float* __restrict__ V, float* __restrict__ A) {
    extern __shared__ __align__(16) unsigned sm_attn[];
    unsigned* QPs = sm_attn;
    unsigned* Ks  = sm_attn + 64 * PSTR;
    unsigned* Vs  = Ks + 64 * KSTR;
    int tid = threadIdx.x, lane = tid & 31, w = tid >> 5;
    int h = blockIdx.y;
    int qt = (int)gridDim.x - 1 - (int)blockIdx.x;
    int q0 = qt * 64;
    const float* Qh  = Q   + ((size_t)h * kT + q0) * kDH;
    const float* KTh = KTr + (size_t)h * kDH * kT;
    const float* Vh  = V   + (size_t)h * kT * kDH;

    #pragma unroll
    for (int it = 0; it < 8; it++) {
        int idx = tid + it * 128;
        int m = idx >> 4, dh4 = (idx & 15) * 4;
        float4 v = *(const float4*)&Qh[(size_t)m * kDH + dh4];
        uint4 u = { f2tf32(v.x), f2tf32(v.y), f2tf32(v.z), f2tf32(v.w) };
        *(uint4*)&QPs[m * PSTR + dh4] = u;
    }
    __syncthreads();
    unsigned qf[8][4];
    {
        int m = w * 16 + (lane >> 2);
        #pragma unroll
        for (int kk = 0; kk < 8; kk++) {
            qf[kk][0] = QPs[m * PSTR + kk * 8 + (lane & 3)];
            qf[kk][1] = QPs[(m + 8) * PSTR + kk * 8 + (lane & 3)];
            qf[kk][2] = QPs[m * PSTR + kk * 8 + 4 + (lane & 3)];
            qf[kk][3] = QPs[(m + 8) * PSTR + kk * 8 + 4 + (lane & 3)];
        }
    }

    float acc_o[8][4] = {};
    float m0 = -1e30f, m1 = -1e30f, l0 = 0.f, l1 = 0.f;

    for (int kt = 0; kt <= qt; kt++) {
        int k0 = kt * 64;
        __syncthreads();
        #pragma unroll
        for (int it = 0; it < 8; it++) {
            int idx = tid + it * 128;
            int dh = idx >> 4, key4 = (idx & 15) * 4;
            float4 v = *(const float4*)&KTh[(size_t)dh * kT + k0 + key4];
            uint4 u = { f2tf32(v.x), f2tf32(v.y), f2tf32(v.z), f2tf32(v.w) };
            *(uint4*)&Ks[dh * KSTR + key4] = u;
        }
        #pragma unroll
        for (int it = 0; it < 8; it++) {
            int idx = tid + it * 128;
            int key = idx >> 4, dh4 = (idx & 15) * 4;
            float4 v = *(const float4*)&Vh[(size_t)(k0 + key) * kDH + dh4];
            uint4 u = { f2tf32(v.x), f2tf32(v.y), f2tf32(v.z), f2tf32(v.w) };
            *(uint4*)&Vs[key * KSTR + dh4] = u;
        }
        __syncthreads();

        float s_acc[8][4] = {};
        #pragma unroll
        for (int kk = 0; kk < 8; kk++) {
            #pragma unroll
            for (int nt = 0; nt < 8; nt++) {
                unsigned bf[2];
                bf[0] = Ks[(kk * 8 + (lane & 3)) * KSTR + nt * 8 + (lane >> 2)];
                bf[1] = Ks[(kk * 8 + 4 + (lane & 3)) * KSTR + nt * 8 + (lane >> 2)];
                mma_tf32(s_acc[nt], qf[kk], bf);
            }
        }

        float rm0 = -1e30f, rm1 = -1e30f;
        int gq0 = q0 + w * 16 + (lane >> 2);
        #pragma unroll
        for (int nt = 0; nt < 8; nt++) {
            #pragma unroll
            for (int c = 0; c < 4; c++) {
                float v = s_acc[nt][c] * 0.125f;
                if (kt == qt) {
                    int key = k0 + nt * 8 + 2 * (lane & 3) + (c & 1);
                    int gq = gq0 + (c >> 1) * 8;
                    if (key > gq) v = -1e30f;
                }
                s_acc[nt][c] = v;
                if ((c >> 1) == 0) rm0 = fmaxf(rm0, v); else rm1 = fmaxf(rm1, v);
            }
        }
        #pragma unroll
        for (int o = 1; o <= 2; o <<= 1) {
            rm0 = fmaxf(rm0, __shfl_xor_sync(0xffffffffu, rm0, o));
            rm1 = fmaxf(rm1, __shfl_xor_sync(0xffffffffu, rm1, o));
        }
        float nm0 = fmaxf(m0, rm0), nm1 = fmaxf(m1, rm1);
        float sc0 = __expf(m0 - nm0), sc1 = __expf(m1 - nm1);
        m0 = nm0; m1 = nm1;

        float rs0 = 0.f, rs1 = 0.f;
        int prow = w * 16 + (lane >> 2);
        #pragma unroll
        for (int nt = 0; nt < 8; nt++) {
            float p0 = __expf(s_acc[nt][0] - nm0);
            float p1 = __expf(s_acc[nt][1] - nm0);
            float p2 = __expf(s_acc[nt][2] - nm1);
            float p3 = __expf(s_acc[nt][3] - nm1);
            rs0 += p0 + p1; rs1 += p2 + p3;
            uint2 u01 = { f2tf32(p0), f2tf32(p1) };
            uint2 u23 = { f2tf32(p2), f2tf32(p3) };
            *(uint2*)&QPs[prow * PSTR + nt * 8 + 2 * (lane & 3)] = u01;
            *(uint2*)&QPs[(prow + 8) * PSTR + nt * 8 + 2 * (lane & 3)] = u23;
        }
        #pragma unroll
        for (int o = 1; o <= 2; o <<= 1) {
            rs0 += __shfl_xor_sync(0xffffffffu, rs0, o);
            rs1 += __shfl_xor_sync(0xffffffffu, rs1, o);
        }
        l0 = l0 * sc0 + rs0;
        l1 = l1 * sc1 + rs1;
        #pragma unroll
        for (int nt = 0; nt < 8; nt++) {
            acc_o[nt][0] *= sc0; acc_o[nt][1] *= sc0;
            acc_o[nt][2] *= sc1; acc_o[nt][3] *= sc1;
        }
        __syncwarp();

        #pragma unroll
        for (int kk = 0; kk < 8; kk++) {
            unsigned pf[4];
            int m = w * 16 + (lane >> 2);
            pf[0] = QPs[m * PSTR + kk * 8 + (lane & 3)];
            pf[1] = QPs[(m + 8) * PSTR + kk * 8 + (lane & 3)];
            pf[2] = QPs[m * PSTR + kk * 8 + 4 + (lane & 3)];
            pf[3] = QPs[(m + 8) * PSTR + kk * 8 + 4 + (lane & 3)];
            #pragma unroll
            for (int nt = 0; nt < 8; nt++) {
                unsigned bf[2];
                bf[0] = Vs[(kk * 8 + (lane & 3)) * KSTR + nt * 8 + (lane >> 2)];
                bf[1] = Vs[(kk * 8 + 4 + (lane & 3)) * KSTR + nt * 8 + (lane >> 2)];
                mma_tf32(acc_o[nt], pf, bf);
            }
        }
    }

    float inv0 = 1.f / l0, inv1 = 1.f / l1;
    int gq0 = q0 + w * 16 + (lane >> 2);
    #pragma unroll
    for (int nt = 0; nt < 8; nt++) {
        int col = h * kDH + nt * 8 + 2 * (lane & 3);
        float2 r0 = { acc_o[nt][0] * inv0, acc_o[nt][1] * inv0 };
        float2 r1 = { acc_o[nt][2] * inv1, acc_o[nt][3] * inv1 };
        *(float2*)&A[(size_t)gq0 * kD + col] = r0;
        *(float2*)&A[(size_t)(gq0 + 8) * kD + col] = r1;
    }
}

// ---------------- proj fp16 GEMM + residual ----------------
__global__ __launch_bounds__(256) void proj_kernel(
    const float* __restrict__ A, const float* __restrict__ W,
    const float* __restrict__ bias, const float* __restrict__ emb,
    float* __restrict__ out) {
    GEMM16_SMEM
    int tid = threadIdx.x, lane = tid & 31, w = tid >> 5;
    int wm = w & 3, wn = w >> 2;
    int r0 = blockIdx.x * 128;
    int n0 = blockIdx.y * 128;

    uint2 pa[4];
    uint4 pb[2];

    #define PROJ_LOAD_REGS(k0_) { \
        _Pragma("unroll") \
        for (int p = 0; p < 4; p++) { \
            int m = (tid >> 3) + p * 32; \
            float4 v = *(const float4*)&A[(size_t)(r0 + m) * kD + (k0_) + (tid & 7) * 4]; \
            pa[p].x = pk2(v.x, v.y); pa[p].y = pk2(v.z, v.w); \
        } \
        _Pragma("unroll") \
        for (int p = 0; p < 2; p++) { \
            int kp = (tid >> 5) + p * 8; \
            const float* b0p = &W[(size_t)((k0_) + 2 * kp) * kD + n0 + (tid & 31) * 4]; \
            float4 r0v = *(const float4*)b0p; \
            float4 r1v = *(const float4*)(b0p + kD); \
            pb[p].x = pk2(r0v.x, r1v.x); pb[p].y = pk2(r0v.y, r1v.y); \
            pb[p].z = pk2(r0v.z, r1v.z); pb[p].w = pk2(r0v.w, r1v.w); \
        } \
    }

    float acc[2][8][4] = {};
    PROJ_LOAD_REGS(0)
    GEMM16_STORE_REGS
    __syncthreads();
    for (int k0 = 0; k0 < kD; k0 += 32) {
        if (k0 + 32 < kD) PROJ_LOAD_REGS(k0 + 32)
        GEMM16_COMPUTE
        __syncthreads();
        if (k0 + 32 < kD) {
            GEMM16_STORE_REGS
            __syncthreads();
        }
    }
    #undef PROJ_LOAD_REGS

    #pragma unroll
    for (int mt = 0; mt < 2; mt++) {
        #pragma unroll
        for (int nt = 0; nt < 8; nt++) {
            int c = n0 + wn * 64 + nt * 8 + (lane & 3) * 2;
            #pragma unroll
            for (int half = 0; half < 2; half++) {
                int r = r0 + wm * 32 + mt * 16 + (lane >> 2) + half * 8;
                float2 e2 = *(const float2*)&emb[(size_t)r * kD + c];
                float2 r2;
                r2.x = e2.x + acc[mt][nt][half * 2 + 0] + bias[c];
                r2.y = e2.y + acc[mt][nt][half * 2 + 1] + bias[c + 1];
                *(float2*)&out[(size_t)r * kD + c] = r2;
            }
        }
    }
}

__global__ void offsets_kernel(float* __restrict__ out, int out_size) {
    if (threadIdx.x == 0 && blockIdx.x == 0) {
        int off = 0;
        g_poff[0] = 0;
        for (int e = 0; e < kE; e++) {
            int pc = (g_counts[e] + 127) & ~127;
            off += pc;
            g_poff[e + 1] = off;
            g_cursor[e] = g_poff[e];
        }
        float aux = 0.f;
        for (int e = 0; e < kE; e++) {
            float imp = g_impsum[e] / (float)kT;
            float dlt = imp - 1.f / (float)kE;
            aux += dlt * dlt;
        }
        aux *= 1.f / (float)kE;
        if (out_size > kT * kD) out[kT * kD] = aux;
    }
}

__global__ void scatter_kernel() {
    int i = blockIdx.x * blockDim.x + threadIdx.x;
    if (i >= kT * 2) return;
    int e = g_ids[i];
    int pos = atomicAdd(&g_cursor[e], 1);
    g_slot_token[pos] = i >> 1;
    g_slotpos[i] = pos;
}

// ---------------- F1 fp16 GEMM: h = relu(y_gathered @ W1[e] + b1[e]) -> fp16 out ----------------
__global__ __launch_bounds__(256) void f1_kernel(
    const float* __restrict__ y, const float* __restrict__ W1,
    const float* __restrict__ b1) {
    GEMM16_SMEM
    __shared__ int tok[128];
    __shared__ int sh_total, sh_e;
    int tid = threadIdx.x, lane = tid & 31, w = tid >> 5;
    int wm = w & 3, wn = w >> 2;
    int s0 = blockIdx.x * 128;
    if (tid == 0) {
        sh_total = g_poff[kE];
        int e = 0;
        while (e < kE - 1 && s0 >= g_poff[e + 1]) e++;
        sh_e = e;
    }
    if (tid < 128) tok[tid] = g_slot_token[s0 + tid];
    __syncthreads();
    if (s0 >= sh_total) return;
    int e = sh_e;
    const float* W = W1 + (size_t)e * kD * kDFF;
    int f0 = blockIdx.y * 128;
    int atok[4];
    #pragma unroll
    for (int p = 0; p < 4; p++) atok[p] = tok[(tid >> 3) + p * 32];

    uint2 pa[4];
    uint4 pb[2];

    #define F1_LOAD_REGS(k0_) { \
        _Pragma("unroll") \
        for (int p = 0; p < 4; p++) { \
            int t = atok[p]; \
            if (t >= 0) { \
                float4 v = *(const float4*)&y[(size_t)t * kD + (k0_) + (tid & 7) * 4]; \
                pa[p].x = pk2(v.x, v.y); pa[p].y = pk2(v.z, v.w); \
            } else { pa[p].x = 0u; pa[p].y = 0u; } \
        } \
        _Pragma("unroll") \
        for (int p = 0; p < 2; p++) { \
            int kp = (tid >> 5) + p * 8; \
            const float* b0p = &W[(size_t)((k0_) + 2 * kp) * kDFF + f0 + (tid & 31) * 4]; \
            float4 r0v = *(const float4*)b0p; \
            float4 r1v = *(const float4*)(b0p + kDFF); \
            pb[p].x = pk2(r0v.x, r1v.x); pb[p].y = pk2(r0v.y, r1v.y); \
            pb[p].z = pk2(r0v.z, r1v.z); pb[p].w = pk2(r0v.w, r1v.w); \
        } \
    }

    float acc[2][8][4] = {};
    F1_LOAD_REGS(0)
    GEMM16_STORE_REGS
    __syncthreads();
    for (int k0 = 0; k0 < kD; k0 += 32) {
        if (k0 + 32 < kD) F1_LOAD_REGS(k0 + 32)
        GEMM16_COMPUTE
        __syncthreads();
        if (k0 + 32 < kD) {
            GEMM16_STORE_REGS
            __syncthreads();
        }
    }
    #undef F1_LOAD_REGS

    #pragma unroll
    for (int mt = 0; mt < 2; mt++) {
        #pragma unroll
        for (int nt = 0; nt < 8; nt++) {
            int c = f0 + wn * 64 + nt * 8 + (lane & 3) * 2;
            float bb0 = b1[(size_t)e * kDFF + c];
            float bb1 = b1[(size_t)e * kDFF + c + 1];
            #pragma unroll
            for (int half = 0; half < 2; half++) {
                int r = s0 + wm * 32 + mt * 16 + (lane >> 2) + half * 8;
                float h0 = fmaxf(acc[mt][nt][half * 2 + 0] + bb0, 0.f);
                float h1 = fmaxf(acc[mt][nt][half * 2 + 1] + bb1, 0.f);
                __half2 hv = __floats2half2_rn(h0, h1);
                *(__half2*)&g_h[(size_t)r * kDFF + c] = hv;
            }
        }
    }
}

// ---------------- F2 fp16 GEMM: yo = h @ W2[e] + b2[e] (A read directly as fp16) ----------------
__global__ __launch_bounds__(256) void f2_kernel(
    const float* __restrict__ W2, const float* __restrict__ b2) {
    GEMM16_SMEM
    __shared__ int sh_total, sh_e;
    int tid = threadIdx.x, lane = tid & 31, w = tid >> 5;
    int wm = w & 3, wn = w >> 2;
    int s0 = blockIdx.x * 128;
    if (tid == 0) {
        sh_total = g_poff[kE];
        int e = 0;
        while (e < kE - 1 && s0 >= g_poff[e + 1]) e++;
        sh_e = e;
    }
    __syncthreads();
    if (s0 >= sh_total) return;
    int e = sh_e;
    const float* W = W2 + (size_t)e * kDFF * kD;
    int c0 = blockIdx.y * 128;

    uint2 pa[4];
    uint4 pb[2];

    #define F2_LOAD_REGS(k0_) { \
        _Pragma("unroll") \
        for (int p = 0; p < 4; p++) { \
            int m = (tid >> 3) + p * 32; \
            pa[p] = *(const uint2*)&g_h[(size_t)(s0 + m) * kDFF + (k0_) + (tid & 7) * 4]; \
        } \
        _Pragma("unroll") \
        for (int p = 0; p < 2; p++) { \
            int kp = (tid >> 5) + p * 8; \
            const float* b0p = &W[(size_t)((k0_) + 2 * kp) * kD + c0 + (tid & 31) * 4]; \
            float4 r0v = *(const float4*)b0p; \
            float4 r1v = *(const float4*)(b0p + kD); \
            pb[p].x = pk2(r0v.x, r1v.x); pb[p].y = pk2(r0v.y, r1v.y); \
            pb[p].z = pk2(r0v.z, r1v.z); pb[p].w = pk2(r0v.w, r1v.w); \
        } \
    }

    float acc[2][8][4] = {};
    F2_LOAD_REGS(0)
    GEMM16_STORE_REGS
    __syncthreads();
    for (int k0 = 0; k0 < kDFF; k0 += 32) {
        if (k0 + 32 < kDFF) F2_LOAD_REGS(k0 + 32)
        GEMM16_COMPUTE
        __syncthreads();
        if (k0 + 32 < kDFF) {
            GEMM16_STORE_REGS
            __syncthreads();
        }
    }
    #undef F2_LOAD_REGS

    #pragma unroll
    for (int mt = 0; mt < 2; mt++) {
        #pragma unroll
        for (int nt = 0; nt < 8; nt++) {
            int c = c0 + wn * 64 + nt * 8 + (lane & 3) * 2;
            float bb0 = b2[(size_t)e * kD + c];
            float bb1 = b2[(size_t)e * kD + c + 1];
            #pragma unroll
            for (int half = 0; half < 2; half++) {
                int r = s0 + wm * 32 + mt * 16 + (lane >> 2) + half * 8;
                float2 r2;
                r2.x = acc[mt][nt][half * 2 + 0] + bb0;
                r2.y = acc[mt][nt][half * 2 + 1] + bb1;
                *(float2*)&g_yo[(size_t)r * kD + c] = r2;
            }
        }
    }
}

// ---------------- combine ----------------
__global__ void combine_kernel(float* __restrict__ out) {
    int idx4 = blockIdx.x * blockDim.x + threadIdx.x;
    if (idx4 >= kT * kD / 4) return;
    int idx = idx4 * 4;
    int n = idx >> 10;
    int d = idx & (kD - 1);
    int p0 = g_slotpos[n * 2], p1 = g_slotpos[n * 2 + 1];
    float g0 = g_gates[n * 2], g1 = g_gates[n * 2 + 1];
    float4 base = *(const float4*)&g_emb2[idx];
    float4 y0 = *(const float4*)&g_yo[(size_t)p0 * kD + d];
    float4 y1 = *(const float4*)&g_yo[(size_t)p1 * kD + d];
    float4 r;
    r.x = base.x + g0 * y0.x + g1 * y1.x;
    r.y = base.y + g0 * y0.y + g1 * y1.y;
    r.z = base.z + g0 * y0.z + g1 * y1.z;
    r.w = base.w + g0 * y0.w + g1 * y1.w;
    *(float4*)&out[idx] = r;
}

// ---------------- launch ----------------
extern "C" void kernel_launch(void* const* d_in, const int* in_sizes, int n_in,
                              void* d_out, int out_size) {
    const float* emb    = (const float*)d_in[0];
    const float* gamma1 = (const float*)d_in[1];
    const float* beta1  = (const float*)d_in[2];
    const float* WQ     = (const float*)d_in[3];
    const float* WK     = (const float*)d_in[4];
    const float* WV     = (const float*)d_in[5];
    const float* Wproj  = (const float*)d_in[6];
    const float* bproj  = (const float*)d_in[7];
    const float* gamma2 = (const float*)d_in[8];
    const float* beta2  = (const float*)d_in[9];
    const float* Wr     = (const float*)d_in[10];
    const float* br     = (const float*)d_in[11];
    const float* W1     = (const float*)d_in[12];
    const float* b1     = (const float*)d_in[13];
    const float* W2     = (const float*)d_in[14];
    const float* b2     = (const float*)d_in[15];
    float* out = (float*)d_out;

    float* gx;    cudaGetSymbolAddress((void**)&gx, g_x);
    float* gq;    cudaGetSymbolAddress((void**)&gq, g_q);
    float* gkT;   cudaGetSymbolAddress((void**)&gkT, g_kT);
    float* gv;    cudaGetSymbolAddress((void**)&gv, g_v);
    float* gattn; cudaGetSymbolAddress((void**)&gattn, g_attn);
    float* gemb2; cudaGetSymbolAddress((void**)&gemb2, g_emb2);
    float* gy;    cudaGetSymbolAddress((void**)&gy, g_y);

    cudaFuncSetAttribute(attn_kernel, cudaFuncAttributeMaxDynamicSharedMemorySize,
                         ATTN_SMEM_BYTES);

    reset_kernel<<<(kSlots + 255) / 256, 256>>>();
    ln_kernel<<<kT, 256>>>(emb, gamma1, beta1, gx);
    qkv_kernel<<<dim3(kT / 128, (kH * kDH) / 128, 3), 256>>>(gx, WQ, WK, WV, gq, gkT, gv);
    attn_kernel<<<dim3(kT / 64, kH), 128, ATTN_SMEM_BYTES>>>(gq, gkT, gv, gattn);
    proj_kernel<<<dim3(kT / 128, kD / 128), 256>>>(gattn, Wproj, bproj, emb, gemb2);
    ln2_router_kernel<<<kT, 256>>>(gemb2, gamma2, beta2, gy, Wr, br);
    offsets_kernel<<<1, 32>>>(out, out_size);
    scatter_kernel<<<(kT * 2 + 255) / 256, 256>>>();
    f1_kernel<<<dim3(kSlots / 128, kDFF / 128), 256>>>(gy, W1, b1);
    f2_kernel<<<dim3(kSlots / 128, kD / 128), 256>>>(W2, b2);
    combine_kernel<<<(kT * kD / 4 + 255) / 256, 256>>>(out);
}

// round 12
// speedup vs baseline: 1.1894x; 1.0819x over previous
#include <cuda_runtime.h>
#include <cuda_fp16.h>
#include <math.h>

// ---------------- problem constants ----------------
constexpr int kT   = 1024;
constexpr int kD   = 1024;
constexpr int kH   = 16;
constexpr int kDH  = 64;
constexpr int kE   = 8;
constexpr int kDFF = 4096;
constexpr int kSlots = 3072;   // 2048 assignments + per-expert pad to 128

// ---------------- device scratch ----------------
__device__ float g_x[kT * kD];
__device__ float g_q[kH * kT * kDH];
__device__ float g_kT[kH * kDH * kT];   // K transposed: [h][dh][t]
__device__ float g_v[kH * kT * kDH];
__device__ float g_attn[kT * kD];
__device__ float g_emb2[kT * kD];
__device__ float g_y[kT * kD];
__device__ __half g_h[kSlots * kDFF];   // expert hidden, fp16
__device__ float g_yo[kSlots * kD];
__device__ int   g_ids[kT * 2];
__device__ float g_gates[kT * 2];
__device__ int   g_counts[kE];
__device__ int   g_poff[kE + 1];
__device__ int   g_cursor[kE];
__device__ int   g_slot_token[kSlots];
__device__ int   g_slotpos[kT * 2];
__device__ float g_impsum[kE];

// ---------------- mma helpers ----------------
__device__ __forceinline__ unsigned f2tf32(float x) {
    unsigned y; asm("cvt.rna.tf32.f32 %0, %1;" : "=r"(y) : "f"(x)); return y;
}
__device__ __forceinline__ void mma_tf32(float c[4], const unsigned a[4], const unsigned b[2]) {
    asm volatile("mma.sync.aligned.m16n8k8.row.col.f32.tf32.tf32.f32 "
        "{%0,%1,%2,%3}, {%4,%5,%6,%7}, {%8,%9}, {%0,%1,%2,%3};\n"
        : "+f"(c[0]), "+f"(c[1]), "+f"(c[2]), "+f"(c[3])
        : "r"(a[0]), "r"(a[1]), "r"(a[2]), "r"(a[3]), "r"(b[0]), "r"(b[1]));
}
__device__ __forceinline__ void mma_f16(float c[4], const unsigned a[4], const unsigned b[2]) {
    asm volatile("mma.sync.aligned.m16n8k16.row.col.f32.f16.f16.f32 "
        "{%0,%1,%2,%3}, {%4,%5,%6,%7}, {%8,%9}, {%0,%1,%2,%3};\n"
        : "+f"(c[0]), "+f"(c[1]), "+f"(c[2]), "+f"(c[3])
        : "r"(a[0]), "r"(a[1]), "r"(a[2]), "r"(a[3]), "r"(b[0]), "r"(b[1]));
}
__device__ __forceinline__ unsigned pk2(float a, float b) {
    __half2 h = __floats2half2_rn(a, b);
    return *(unsigned*)&h;
}

// fp16 GEMM tile config: block 256 threads, tile M=128 N=128, warp tile 32x64,
// K-panel 32 (= 2 k16 MMAs), DOUBLE-BUFFERED smem (1 sync per panel).
constexpr int ASTR = 20;
constexpr int BSTR = 136;

#define GEMM16_SMEM \
    __shared__ __align__(16) unsigned As[2][128 * ASTR]; \
    __shared__ __align__(16) unsigned Bs[2][16 * BSTR];

// compute one 32-deep panel from buffer `buf`
#define GEMM16_COMPUTE(buf) \
    _Pragma("unroll") \
    for (int p0 = 0; p0 < 16; p0 += 8) { \
        unsigned bf[8][2]; \
        _Pragma("unroll") \
        for (int nt = 0; nt < 8; nt++) { \
            int n = wn * 64 + nt * 8 + (lane >> 2); \
            bf[nt][0] = Bs[buf][(p0 + (lane & 3)) * BSTR + n]; \
            bf[nt][1] = Bs[buf][(p0 + 4 + (lane & 3)) * BSTR + n]; \
        } \
        _Pragma("unroll") \
        for (int mt = 0; mt < 2; mt++) { \
            int m = wm * 32 + mt * 16 + (lane >> 2); \
            unsigned af[4]; \
            af[0] = As[buf][m * ASTR + p0 + (lane & 3)]; \
            af[1] = As[buf][(m + 8) * ASTR + p0 + (lane & 3)]; \
            af[2] = As[buf][m * ASTR + p0 + 4 + (lane & 3)]; \
            af[3] = As[buf][(m + 8) * ASTR + p0 + 4 + (lane & 3)]; \
            _Pragma("unroll") \
            for (int nt = 0; nt < 8; nt++) mma_f16(acc[mt][nt], af, bf[nt]); \
        } \
    }

// store prefetched regs (pa[4] uint2, pb[2] uint4) into buffer `buf` (256 threads)
#define GEMM16_STORE_REGS(buf) \
    _Pragma("unroll") \
    for (int p = 0; p < 4; p++) \
        *(uint2*)&As[buf][((tid >> 3) + p * 32) * ASTR + (tid & 7) * 2] = pa[p]; \
    _Pragma("unroll") \
    for (int p = 0; p < 2; p++) \
        *(uint4*)&Bs[buf][((tid >> 5) + p * 8) * BSTR + (tid & 31) * 4] = pb[p];

// ---------------- misc helpers ----------------
__device__ __forceinline__ float block_reduce_sum(float v) {
    __shared__ float sh[32];
    int lane = threadIdx.x & 31, w = threadIdx.x >> 5;
    #pragma unroll
    for (int o = 16; o > 0; o >>= 1) v += __shfl_xor_sync(0xffffffffu, v, o);
    if (lane == 0) sh[w] = v;
    __syncthreads();
    if (w == 0) {
        v = (lane < (int)(blockDim.x >> 5)) ? sh[lane] : 0.f;
        #pragma unroll
        for (int o = 16; o > 0; o >>= 1) v += __shfl_xor_sync(0xffffffffu, v, o);
        if (lane == 0) sh[0] = v;
    }
    __syncthreads();
    float r = sh[0];
    __syncthreads();
    return r;
}

// ---------------- LN1 (+ folded scratch reset) ----------------
__global__ void ln_kernel(const float* __restrict__ in, const float* __restrict__ g,
                          const float* __restrict__ b, float* __restrict__ out) {
    // folded reset: runs long before any consumer (router/scatter/f1)
    int gi = blockIdx.x * blockDim.x + threadIdx.x;
    if (gi < kSlots) g_slot_token[gi] = -1;
    if (gi < kE) { g_counts[gi] = 0; g_impsum[gi] = 0.f; }

    int row = blockIdx.x;
    const float* x = in + (size_t)row * kD;
    float s = 0.f;
    for (int i = threadIdx.x; i < kD; i += blockDim.x) s += x[i];
    float mean = block_reduce_sum(s) * (1.f / kD);
    float v = 0.f;
    for (int i = threadIdx.x; i < kD; i += blockDim.x) {
        float d = x[i] - mean; v += d * d;
    }
    float var = block_reduce_sum(v) * (1.f / kD);
    float rstd = rsqrtf(var + 1e-6f);
    float* o = out + (size_t)row * kD;
    for (int i = threadIdx.x; i < kD; i += blockDim.x)
        o[i] = (x[i] - mean) * rstd * g[i] + b[i];
}

// ---------------- fused LN2 + router: block per token row ----------------
__global__ void ln2_router_kernel(const float* __restrict__ in,
                                  const float* __restrict__ g, const float* __restrict__ b,
                                  float* __restrict__ out,
                                  const float* __restrict__ Wr, const float* __restrict__ br) {
    int row = blockIdx.x;
    const float* x = in + (size_t)row * kD;
    float s = 0.f;
    for (int i = threadIdx.x; i < kD; i += blockDim.x) s += x[i];
    float mean = block_reduce_sum(s) * (1.f / kD);
    float v = 0.f;
    for (int i = threadIdx.x; i < kD; i += blockDim.x) {
        float d = x[i] - mean; v += d * d;
    }
    float var = block_reduce_sum(v) * (1.f / kD);
    float rstd = rsqrtf(var + 1e-6f);
    float* o = out + (size_t)row * kD;
    float rs[kE];
    #pragma unroll
    for (int e = 0; e < kE; e++) rs[e] = 0.f;
    for (int i = threadIdx.x; i < kD; i += blockDim.x) {
        float val = (x[i] - mean) * rstd * g[i] + b[i];
        o[i] = val;
        const float* wr = Wr + (size_t)i * kE;
        #pragma unroll
        for (int e = 0; e < kE; e++) rs[e] += val * wr[e];
    }
    #pragma unroll
    for (int e = 0; e < kE; e++) rs[e] = block_reduce_sum(rs[e]);
    if (threadIdx.x == 0) {
        float w[kE];
        float mx = -1e30f;
        #pragma unroll
        for (int e = 0; e < kE; e++) { w[e] = rs[e] + br[e]; mx = fmaxf(mx, w[e]); }
        float sum = 0.f;
        #pragma unroll
        for (int e = 0; e < kE; e++) { w[e] = __expf(w[e] - mx); sum += w[e]; }
        float inv = 1.f / sum;
        #pragma unroll
        for (int e = 0; e < kE; e++) w[e] *= inv;
        int i0 = 0;
        #pragma unroll
        for (int e = 1; e < kE; e++) if (w[e] > w[i0]) i0 = e;
        int i1 = -1;
        #pragma unroll
        for (int e = 0; e < kE; e++) if (e != i0 && (i1 < 0 || w[e] > w[i1])) i1 = e;
        float norm = w[i0] + w[i1];
        g_ids[row * 2]     = i0;
        g_ids[row * 2 + 1] = i1;
        g_gates[row * 2]     = w[i0] / norm;
        g_gates[row * 2 + 1] = w[i1] / norm;
        atomicAdd(&g_counts[i0], 1);
        atomicAdd(&g_counts[i1], 1);
        #pragma unroll
        for (int e = 0; e < kE; e++) atomicAdd(&g_impsum[e], w[e]);
    }
}

// ---------------- QKV fp16 GEMM + fused RoPE (K written transposed) ----------------
__global__ __launch_bounds__(256) void qkv_kernel(
    const float* __restrict__ x,
    const float* __restrict__ WQ, const float* __restrict__ WK, const float* __restrict__ WV,
    float* __restrict__ Qo, float* __restrict__ KTo, float* __restrict__ Vo) {
    GEMM16_SMEM
    int tid = threadIdx.x, lane = tid & 31, w = tid >> 5;
    int wm = w & 3, wn = w >> 2;
    int r0 = blockIdx.x * 128;
    int n0 = blockIdx.y * 128;
    int z = blockIdx.z;
    const float* W = (z == 0) ? WQ : (z == 1) ? WK : WV;

    int bn4 = (tid & 31) * 4;
    int bh = (n0 + bn4) >> 6, be = (n0 + bn4) & 63;
    uint2 pa[4];
    uint4 pb[2];

    #define QKV_LOAD_REGS(k0_) { \
        _Pragma("unroll") \
        for (int p = 0; p < 4; p++) { \
            int m = (tid >> 3) + p * 32; \
            float4 v = *(const float4*)&x[(size_t)(r0 + m) * kD + (k0_) + (tid & 7) * 4]; \
            pa[p].x = pk2(v.x, v.y); pa[p].y = pk2(v.z, v.w); \
        } \
        _Pragma("unroll") \
        for (int p = 0; p < 2; p++) { \
            int kp = (tid >> 5) + p * 8; \
            const float* b0p = &W[((size_t)bh * kD + (k0_) + 2 * kp) * kDH + be]; \
            float4 r0v = *(const float4*)b0p; \
            float4 r1v = *(const float4*)(b0p + kDH); \
            pb[p].x = pk2(r0v.x, r1v.x); pb[p].y = pk2(r0v.y, r1v.y); \
            pb[p].z = pk2(r0v.z, r1v.z); pb[p].w = pk2(r0v.w, r1v.w); \
        } \
    }

    float acc[2][8][4] = {};
    QKV_LOAD_REGS(0)
    GEMM16_STORE_REGS(0)
    __syncthreads();
    for (int k0 = 0, i = 0; k0 < kD; k0 += 32, i++) {
        if (k0 + 32 < kD) QKV_LOAD_REGS(k0 + 32)
        GEMM16_COMPUTE(i & 1)
        if (k0 + 32 < kD) GEMM16_STORE_REGS((i + 1) & 1)
        __syncthreads();
    }
    #undef QKV_LOAD_REGS

    #pragma unroll
    for (int mt = 0; mt < 2; mt++) {
        #pragma unroll
        for (int nt = 0; nt < 8; nt++) {
            int n = n0 + wn * 64 + nt * 8 + (lane & 3) * 2;
            int h = n >> 6, e = n & 63;
            #pragma unroll
            for (int half = 0; half < 2; half++) {
                int t = r0 + wm * 32 + mt * 16 + (lane >> 2) + half * 8;
                float v0 = acc[mt][nt][half * 2 + 0];
                float v1 = acc[mt][nt][half * 2 + 1];
                if (z < 2) {
                    int p = e >> 1;
                    float theta = exp2f(-(float)p * (13.287712379549449f / 32.f));
                    float sn, cs;
                    sincosf((float)t * theta, &sn, &cs);
                    float w0 = v0 * cs - v1 * sn;
                    float w1 = v1 * cs + v0 * sn;
                    v0 = w0; v1 = w1;
                }
                if (z == 1) {
                    KTo[((size_t)h * kDH + e) * kT + t]     = v0;
                    KTo[((size_t)h * kDH + e + 1) * kT + t] = v1;
                } else {
                    float* O = (z == 0) ? Qo : Vo;
                    float2 r2 = { v0, v1 };
                    *(float2*)&O[((size_t)h * kT + t) * kDH + e] = r2;
                }
            }
        }
    }
}

// ---------------- flash attention (tf32 mma): block = (64 q-rows, head), 4 warps ----------------
constexpr int KSTR = 72;
constexpr int PSTR = 68;
constexpr int ATTN_SMEM_BYTES = (64 * PSTR + 2 * 64 * KSTR) * 4;   // 54272

__global__ __launch_bounds__(128) void attn_kernel(
    const float* __restrict__ Q, const float* __restrict__ KTr,
    const float* __restrict__ V, float* __restrict__ A) {
    extern __shared__ __align__(16) unsigned sm_attn[];
    unsigned* QPs = sm_attn;
    unsigned* Ks  = sm_attn + 64 * PSTR;
    unsigned* Vs  = Ks + 64 * KSTR;
    int tid = threadIdx.x, lane = tid & 31, w = tid >> 5;
    int h = blockIdx.y;
    int qt = (int)gridDim.x - 1 - (int)blockIdx.x;
    int q0 = qt * 64;
    const float* Qh  = Q   + ((size_t)h * kT + q0) * kDH;
    const float* KTh = KTr + (size_t)h * kDH * kT;
    const float* Vh  = V   + (size_t)h * kT * kDH;

    #pragma unroll
    for (int it = 0; it < 8; it++) {
        int idx = tid + it * 128;
        int m = idx >> 4, dh4 = (idx & 15) * 4;
        float4 v = *(const float4*)&Qh[(size_t)m * kDH + dh4];
        uint4 u = { f2tf32(v.x), f2tf32(v.y), f2tf32(v.z), f2tf32(v.w) };
        *(uint4*)&QPs[m * PSTR + dh4] = u;
    }
    __syncthreads();
    unsigned qf[8][4];
    {
        int m = w * 16 + (lane >> 2);
        #pragma unroll
        for (int kk = 0; kk < 8; kk++) {
            qf[kk][0] = QPs[m * PSTR + kk * 8 + (lane & 3)];
            qf[kk][1] = QPs[(m + 8) * PSTR + kk * 8 + (lane & 3)];
            qf[kk][2] = QPs[m * PSTR + kk * 8 + 4 + (lane & 3)];
            qf[kk][3] = QPs[(m + 8) * PSTR + kk * 8 + 4 + (lane & 3)];
        }
    }

    float acc_o[8][4] = {};
    float m0 = -1e30f, m1 = -1e30f, l0 = 0.f, l1 = 0.f;

    for (int kt = 0; kt <= qt; kt++) {
        int k0 = kt * 64;
        __syncthreads();
        #pragma unroll
        for (int it = 0; it < 8; it++) {
            int idx = tid + it * 128;
            int dh = idx >> 4, key4 = (idx & 15) * 4;
            float4 v = *(const float4*)&KTh[(size_t)dh * kT + k0 + key4];
            uint4 u = { f2tf32(v.x), f2tf32(v.y), f2tf32(v.z), f2tf32(v.w) };
            *(uint4*)&Ks[dh * KSTR + key4] = u;
        }
        #pragma unroll
        for (int it = 0; it < 8; it++) {
            int idx = tid + it * 128;
            int key = idx >> 4, dh4 = (idx & 15) * 4;
            float4 v = *(const float4*)&Vh[(size_t)(k0 + key) * kDH + dh4];
            uint4 u = { f2tf32(v.x), f2tf32(v.y), f2tf32(v.z), f2tf32(v.w) };
            *(uint4*)&Vs[key * KSTR + dh4] = u;
        }
        __syncthreads();

        float s_acc[8][4] = {};
        #pragma unroll
        for (int kk = 0; kk < 8; kk++) {
            #pragma unroll
            for (int nt = 0; nt < 8; nt++) {
                unsigned bf[2];
                bf[0] = Ks[(kk * 8 + (lane & 3)) * KSTR + nt * 8 + (lane >> 2)];
                bf[1] = Ks[(kk * 8 + 4 + (lane & 3)) * KSTR + nt * 8 + (lane >> 2)];
                mma_tf32(s_acc[nt], qf[kk], bf);
            }
        }

        float rm0 = -1e30f, rm1 = -1e30f;
        int gq0 = q0 + w * 16 + (lane >> 2);
        #pragma unroll
        for (int nt = 0; nt < 8; nt++) {
            #pragma unroll
            for (int c = 0; c < 4; c++) {
                float v = s_acc[nt][c] * 0.125f;
                if (kt == qt) {
                    int key = k0 + nt * 8 + 2 * (lane & 3) + (c & 1);
                    int gq = gq0 + (c >> 1) * 8;
                    if (key > gq) v = -1e30f;
                }
                s_acc[nt][c] = v;
                if ((c >> 1) == 0) rm0 = fmaxf(rm0, v); else rm1 = fmaxf(rm1, v);
            }
        }
        #pragma unroll
        for (int o = 1; o <= 2; o <<= 1) {
            rm0 = fmaxf(rm0, __shfl_xor_sync(0xffffffffu, rm0, o));
            rm1 = fmaxf(rm1, __shfl_xor_sync(0xffffffffu, rm1, o));
        }
        float nm0 = fmaxf(m0, rm0), nm1 = fmaxf(m1, rm1);
        float sc0 = __expf(m0 - nm0), sc1 = __expf(m1 - nm1);
        m0 = nm0; m1 = nm1;

        float rs0 = 0.f, rs1 = 0.f;
        int prow = w * 16 + (lane >> 2);
        #pragma unroll
        for (int nt = 0; nt < 8; nt++) {
            float p0 = __expf(s_acc[nt][0] - nm0);
            float p1 = __expf(s_acc[nt][1] - nm0);
            float p2 = __expf(s_acc[nt][2] - nm1);
            float p3 = __expf(s_acc[nt][3] - nm1);
            rs0 += p0 + p1; rs1 += p2 + p3;
            uint2 u01 = { f2tf32(p0), f2tf32(p1) };
            uint2 u23 = { f2tf32(p2), f2tf32(p3) };
            *(uint2*)&QPs[prow * PSTR + nt * 8 + 2 * (lane & 3)] = u01;
            *(uint2*)&QPs[(prow + 8) * PSTR + nt * 8 + 2 * (lane & 3)] = u23;
        }
        #pragma unroll
        for (int o = 1; o <= 2; o <<= 1) {
            rs0 += __shfl_xor_sync(0xffffffffu, rs0, o);
            rs1 += __shfl_xor_sync(0xffffffffu, rs1, o);
        }
        l0 = l0 * sc0 + rs0;
        l1 = l1 * sc1 + rs1;
        #pragma unroll
        for (int nt = 0; nt < 8; nt++) {
            acc_o[nt][0] *= sc0; acc_o[nt][1] *= sc0;
            acc_o[nt][2] *= sc1; acc_o[nt][3] *= sc1;
        }
        __syncwarp();

        #pragma unroll
        for (int kk = 0; kk < 8; kk++) {
            unsigned pf[4];
            int m = w * 16 + (lane >> 2);
            pf[0] = QPs[m * PSTR + kk * 8 + (lane & 3)];
            pf[1] = QPs[(m + 8) * PSTR + kk * 8 + (lane & 3)];
            pf[2] = QPs[m * PSTR + kk * 8 + 4 + (lane & 3)];
            pf[3] = QPs[(m + 8) * PSTR + kk * 8 + 4 + (lane & 3)];
            #pragma unroll
            for (int nt = 0; nt < 8; nt++) {
                unsigned bf[2];
                bf[0] = Vs[(kk * 8 + (lane & 3)) * KSTR + nt * 8 + (lane >> 2)];
                bf[1] = Vs[(kk * 8 + 4 + (lane & 3)) * KSTR + nt * 8 + (lane >> 2)];
                mma_tf32(acc_o[nt], pf, bf);
            }
        }
    }

    float inv0 = 1.f / l0, inv1 = 1.f / l1;
    int gq0 = q0 + w * 16 + (lane >> 2);
    #pragma unroll
    for (int nt = 0; nt < 8; nt++) {
        int col = h * kDH + nt * 8 + 2 * (lane & 3);
        float2 r0 = { acc_o[nt][0] * inv0, acc_o[nt][1] * inv0 };
        float2 r1 = { acc_o[nt][2] * inv1, acc_o[nt][3] * inv1 };
        *(float2*)&A[(size_t)gq0 * kD + col] = r0;
        *(float2*)&A[(size_t)(gq0 + 8) * kD + col] = r1;
    }
}

// ---------------- proj fp16 GEMM + residual ----------------
__global__ __launch_bounds__(256) void proj_kernel(
    const float* __restrict__ A, const float* __restrict__ W,
    const float* __restrict__ bias, const float* __restrict__ emb,
    float* __restrict__ out) {
    GEMM16_SMEM
    int tid = threadIdx.x, lane = tid & 31, w = tid >> 5;
    int wm = w & 3, wn = w >> 2;
    int r0 = blockIdx.x * 128;
    int n0 = blockIdx.y * 128;

    uint2 pa[4];
    uint4 pb[2];

    #define PROJ_LOAD_REGS(k0_) { \
        _Pragma("unroll") \
        for (int p = 0; p < 4; p++) { \
            int m = (tid >> 3) + p * 32; \
            float4 v = *(const float4*)&A[(size_t)(r0 + m) * kD + (k0_) + (tid & 7) * 4]; \
            pa[p].x = pk2(v.x, v.y); pa[p].y = pk2(v.z, v.w); \
        } \
        _Pragma("unroll") \
        for (int p = 0; p < 2; p++) { \
            int kp = (tid >> 5) + p * 8; \
            const float* b0p = &W[(size_t)((k0_) + 2 * kp) * kD + n0 + (tid & 31) * 4]; \
            float4 r0v = *(const float4*)b0p; \
            float4 r1v = *(const float4*)(b0p + kD); \
            pb[p].x = pk2(r0v.x, r1v.x); pb[p].y = pk2(r0v.y, r1v.y); \
            pb[p].z = pk2(r0v.z, r1v.z); pb[p].w = pk2(r0v.w, r1v.w); \
        } \
    }

    float acc[2][8][4] = {};
    PROJ_LOAD_REGS(0)
    GEMM16_STORE_REGS(0)
    __syncthreads();
    for (int k0 = 0, i = 0; k0 < kD; k0 += 32, i++) {
        if (k0 + 32 < kD) PROJ_LOAD_REGS(k0 + 32)
        GEMM16_COMPUTE(i & 1)
        if (k0 + 32 < kD) GEMM16_STORE_REGS((i + 1) & 1)
        __syncthreads();
    }
    #undef PROJ_LOAD_REGS

    #pragma unroll
    for (int mt = 0; mt < 2; mt++) {
        #pragma unroll
        for (int nt = 0; nt < 8; nt++) {
            int c = n0 + wn * 64 + nt * 8 + (lane & 3) * 2;
            #pragma unroll
            for (int half = 0; half < 2; half++) {
                int r = r0 + wm * 32 + mt * 16 + (lane >> 2) + half * 8;
                float2 e2 = *(const float2*)&emb[(size_t)r * kD + c];
                float2 r2;
                r2.x = e2.x + acc[mt][nt][half * 2 + 0] + bias[c];
                r2.y = e2.y + acc[mt][nt][half * 2 + 1] + bias[c + 1];
                *(float2*)&out[(size_t)r * kD + c] = r2;
            }
        }
    }
}

// ---------------- fused offsets + aux + scatter (single block) ----------------
__global__ void offsets_scatter_kernel(float* __restrict__ out, int out_size) {
    int tid = threadIdx.x;
    if (tid == 0) {
        int off = 0;
        g_poff[0] = 0;
        for (int e = 0; e < kE; e++) {
            int pc = (g_counts[e] + 127) & ~127;
            off += pc;
            g_poff[e + 1] = off;
            g_cursor[e] = g_poff[e];
        }
        float aux = 0.f;
        for (int e = 0; e < kE; e++) {
            float imp = g_impsum[e] / (float)kT;
            float dlt = imp - 1.f / (float)kE;
            aux += dlt * dlt;
        }
        aux *= 1.f / (float)kE;
        if (out_size > kT * kD) out[kT * kD] = aux;
    }
    __syncthreads();
    for (int i = tid; i < kT * 2; i += blockDim.x) {
        int e = g_ids[i];
        int pos = atomicAdd(&g_cursor[e], 1);
        g_slot_token[pos] = i >> 1;
        g_slotpos[i] = pos;
    }
}

// ---------------- F1 fp16 GEMM: h = relu(y_gathered @ W1[e] + b1[e]) -> fp16 out ----------------
__global__ __launch_bounds__(256) void f1_kernel(
    const float* __restrict__ y, const float* __restrict__ W1,
    const float* __restrict__ b1) {
    GEMM16_SMEM
    __shared__ int tok[128];
    __shared__ int sh_total, sh_e;
    int tid = threadIdx.x, lane = tid & 31, w = tid >> 5;
    int wm = w & 3, wn = w >> 2;
    int s0 = blockIdx.x * 128;
    if (tid == 0) {
        sh_total = g_poff[kE];
        int e = 0;
        while (e < kE - 1 && s0 >= g_poff[e + 1]) e++;
        sh_e = e;
    }
    if (tid < 128) tok[tid] = g_slot_token[s0 + tid];
    __syncthreads();
    if (s0 >= sh_total) return;
    int e = sh_e;
    const float* W = W1 + (size_t)e * kD * kDFF;
    int f0 = blockIdx.y * 128;
    int atok[4];
    #pragma unroll
    for (int p = 0; p < 4; p++) atok[p] = tok[(tid >> 3) + p * 32];

    uint2 pa[4];
    uint4 pb[2];

    #define F1_LOAD_REGS(k0_) { \
        _Pragma("unroll") \
        for (int p = 0; p < 4; p++) { \
            int t = atok[p]; \
            if (t >= 0) { \
                float4 v = *(const float4*)&y[(size_t)t * kD + (k0_) + (tid & 7) * 4]; \
                pa[p].x = pk2(v.x, v.y); pa[p].y = pk2(v.z, v.w); \
            } else { pa[p].x = 0u; pa[p].y = 0u; } \
        } \
        _Pragma("unroll") \
        for (int p = 0; p < 2; p++) { \
            int kp = (tid >> 5) + p * 8; \
            const float* b0p = &W[(size_t)((k0_) + 2 * kp) * kDFF + f0 + (tid & 31) * 4]; \
            float4 r0v = *(const float4*)b0p; \
            float4 r1v = *(const float4*)(b0p + kDFF); \
            pb[p].x = pk2(r0v.x, r1v.x); pb[p].y = pk2(r0v.y, r1v.y); \
            pb[p].z = pk2(r0v.z, r1v.z); pb[p].w = pk2(r0v.w, r1v.w); \
        } \
    }

    float acc[2][8][4] = {};
    F1_LOAD_REGS(0)
    GEMM16_STORE_REGS(0)
    __syncthreads();
    for (int k0 = 0, i = 0; k0 < kD; k0 += 32, i++) {
        if (k0 + 32 < kD) F1_LOAD_REGS(k0 + 32)
        GEMM16_COMPUTE(i & 1)
        if (k0 + 32 < kD) GEMM16_STORE_REGS((i + 1) & 1)
        __syncthreads();
    }
    #undef F1_LOAD_REGS

    #pragma unroll
    for (int mt = 0; mt < 2; mt++) {
        #pragma unroll
        for (int nt = 0; nt < 8; nt++) {
            int c = f0 + wn * 64 + nt * 8 + (lane & 3) * 2;
            float bb0 = b1[(size_t)e * kDFF + c];
            float bb1 = b1[(size_t)e * kDFF + c + 1];
            #pragma unroll
            for (int half = 0; half < 2; half++) {
                int r = s0 + wm * 32 + mt * 16 + (lane >> 2) + half * 8;
                float h0 = fmaxf(acc[mt][nt][half * 2 + 0] + bb0, 0.f);
                float h1 = fmaxf(acc[mt][nt][half * 2 + 1] + bb1, 0.f);
                __half2 hv = __floats2half2_rn(h0, h1);
                *(__half2*)&g_h[(size_t)r * kDFF + c] = hv;
            }
        }
    }
}

// ---------------- F2 fp16 GEMM: yo = h @ W2[e] + b2[e] (A read directly as fp16) ----------------
__global__ __launch_bounds__(256) void f2_kernel(
    const float* __restrict__ W2, const float* __restrict__ b2) {
    GEMM16_SMEM
    __shared__ int sh_total, sh_e;
    int tid = threadIdx.x, lane = tid & 31, w = tid >> 5;
    int wm = w & 3, wn = w >> 2;
    int s0 = blockIdx.x * 128;
    if (tid == 0) {
        sh_total = g_poff[kE];
        int e = 0;
        while (e < kE - 1 && s0 >= g_poff[e + 1]) e++;
        sh_e = e;
    }
    __syncthreads();
    if (s0 >= sh_total) return;
    int e = sh_e;
    const float* W = W2 + (size_t)e * kDFF * kD;
    int c0 = blockIdx.y * 128;

    uint2 pa[4];
    uint4 pb[2];

    #define F2_LOAD_REGS(k0_) { \
        _Pragma("unroll") \
        for (int p = 0; p < 4; p++) { \
            int m = (tid >> 3) + p * 32; \
            pa[p] = *(const uint2*)&g_h[(size_t)(s0 + m) * kDFF + (k0_) + (tid & 7) * 4]; \
        } \
        _Pragma("unroll") \
        for (int p = 0; p < 2; p++) { \
            int kp = (tid >> 5) + p * 8; \
            const float* b0p = &W[(size_t)((k0_) + 2 * kp) * kD + c0 + (tid & 31) * 4]; \
            float4 r0v = *(const float4*)b0p; \
            float4 r1v = *(const float4*)(b0p + kD); \
            pb[p].x = pk2(r0v.x, r1v.x); pb[p].y = pk2(r0v.y, r1v.y); \
            pb[p].z = pk2(r0v.z, r1v.z); pb[p].w = pk2(r0v.w, r1v.w); \
        } \
    }

    float acc[2][8][4] = {};
    F2_LOAD_REGS(0)
    GEMM16_STORE_REGS(0)
    __syncthreads();
    for (int k0 = 0, i = 0; k0 < kDFF; k0 += 32, i++) {
        if (k0 + 32 < kDFF) F2_LOAD_REGS(k0 + 32)
        GEMM16_COMPUTE(i & 1)
        if (k0 + 32 < kDFF) GEMM16_STORE_REGS((i + 1) & 1)
        __syncthreads();
    }
    #undef F2_LOAD_REGS

    #pragma unroll
    for (int mt = 0; mt < 2; mt++) {
        #pragma unroll
        for (int nt = 0; nt < 8; nt++) {
            int c = c0 + wn * 64 + nt * 8 + (lane & 3) * 2;
            float bb0 = b2[(size_t)e * kD + c];
            float bb1 = b2[(size_t)e * kD + c + 1];
            #pragma unroll
            for (int half = 0; half < 2; half++) {
                int r = s0 + wm * 32 + mt * 16 + (lane >> 2) + half * 8;
                float2 r2;
                r2.x = acc[mt][nt][half * 2 + 0] + bb0;
                r2.y = acc[mt][nt][half * 2 + 1] + bb1;
                *(float2*)&g_yo[(size_t)r * kD + c] = r2;
            }
        }
    }
}

// ---------------- combine ----------------
__global__ void combine_kernel(float* __restrict__ out) {
    int idx4 = blockIdx.x * blockDim.x + threadIdx.x;
    if (idx4 >= kT * kD / 4) return;
    int idx = idx4 * 4;
    int n = idx >> 10;
    int d = idx & (kD - 1);
    int p0 = g_slotpos[n * 2], p1 = g_slotpos[n * 2 + 1];
    float g0 = g_gates[n * 2], g1 = g_gates[n * 2 + 1];
    float4 base = *(const float4*)&g_emb2[idx];
    float4 y0 = *(const float4*)&g_yo[(size_t)p0 * kD + d];
    float4 y1 = *(const float4*)&g_yo[(size_t)p1 * kD + d];
    float4 r;
    r.x = base.x + g0 * y0.x + g1 * y1.x;
    r.y = base.y + g0 * y0.y + g1 * y1.y;
    r.z = base.z + g0 * y0.z + g1 * y1.z;
    r.w = base.w + g0 * y0.w + g1 * y1.w;
    *(float4*)&out[idx] = r;
}

// ---------------- launch ----------------
extern "C" void kernel_launch(void* const* d_in, const int* in_sizes, int n_in,
                              void* d_out, int out_size) {
    const float* emb    = (const float*)d_in[0];
    const float* gamma1 = (const float*)d_in[1];
    const float* beta1  = (const float*)d_in[2];
    const float* WQ     = (const float*)d_in[3];
    const float* WK     = (const float*)d_in[4];
    const float* WV     = (const float*)d_in[5];
    const float* Wproj  = (const float*)d_in[6];
    const float* bproj  = (const float*)d_in[7];
    const float* gamma2 = (const float*)d_in[8];
    const float* beta2  = (const float*)d_in[9];
    const float* Wr     = (const float*)d_in[10];
    const float* br     = (const float*)d_in[11];
    const float* W1     = (const float*)d_in[12];
    const float* b1     = (const float*)d_in[13];
    const float* W2     = (const float*)d_in[14];
    const float* b2     = (const float*)d_in[15];
    float* out = (float*)d_out;

    float* gx;    cudaGetSymbolAddress((void**)&gx, g_x);
    float* gq;    cudaGetSymbolAddress((void**)&gq, g_q);
    float* gkT;   cudaGetSymbolAddress((void**)&gkT, g_kT);
    float* gv;    cudaGetSymbolAddress((void**)&gv, g_v);
    float* gattn; cudaGetSymbolAddress((void**)&gattn, g_attn);
    float* gemb2; cudaGetSymbolAddress((void**)&gemb2, g_emb2);
    float* gy;    cudaGetSymbolAddress((void**)&gy, g_y);

    cudaFuncSetAttribute(attn_kernel, cudaFuncAttributeMaxDynamicSharedMemorySize,
                         ATTN_SMEM_BYTES);

    ln_kernel<<<kT, 256>>>(emb, gamma1, beta1, gx);
    qkv_kernel<<<dim3(kT / 128, (kH * kDH) / 128, 3), 256>>>(gx, WQ, WK, WV, gq, gkT, gv);
    attn_kernel<<<dim3(kT / 64, kH), 128, ATTN_SMEM_BYTES>>>(gq, gkT, gv, gattn);
    proj_kernel<<<dim3(kT / 128, kD / 128), 256>>>(gattn, Wproj, bproj, emb, gemb2);
    ln2_router_kernel<<<kT, 256>>>(gemb2, gamma2, beta2, gy, Wr, br);
    offsets_scatter_kernel<<<1, 1024>>>(out, out_size);
    f1_kernel<<<dim3(kSlots / 128, kDFF / 128), 256>>>(gy, W1, b1);
    f2_kernel<<<dim3(kSlots / 128, kD / 128), 256>>>(W2, b2);
    combine_kernel<<<(kT * kD / 4 + 255) / 256, 256>>>(out);
}